// round 1
// baseline (speedup 1.0000x reference)
#include <cuda_runtime.h>
#include <cuda_bf16.h>

// Problem constants (fixed by the dataset)
#define NN 100000
#define EE 500000
#define NF 128
#define ATTR_W 16
#define STATE_W 12
#define REL_W 4
#define PSTEP 2

// Scratch (device globals; no runtime allocation allowed)
__device__ float g_pe [NN * NF];   // particle encoding   [N,128]
__device__ float g_ee [EE * NF];   // edge encoding       [E,128]
__device__ float g_eff[NN * NF];   // particle effect     [N,128]
__device__ float g_agg[NN * NF];   // segment-sum target  [N,128]

// ---------------------------------------------------------------------------
// zero kernel
// ---------------------------------------------------------------------------
__global__ void k_zero(float* p, int n) {
    int i = blockIdx.x * blockDim.x + threadIdx.x;
    int stride = gridDim.x * blockDim.x;
    for (; i < n; i += stride) p[i] = 0.0f;
}

// ---------------------------------------------------------------------------
// Node encoder: pe = relu(relu([attr,state] @ w1 + b1) @ w2 + b2)
// 128 threads = output features, RB rows per block.
// ---------------------------------------------------------------------------
__global__ __launch_bounds__(128) void k_node_enc(
    const float* __restrict__ attr, const float* __restrict__ state,
    const float* __restrict__ w1, const float* __restrict__ b1,
    const float* __restrict__ w2, const float* __restrict__ b2,
    float* __restrict__ pe, int n)
{
    const int RB = 8;
    const int KIN = ATTR_W + STATE_W; // 28
    __shared__ float s_in[RB][KIN];
    __shared__ float s_h1[RB][NF];

    int row0 = blockIdx.x * RB;
    int t = threadIdx.x;

    for (int i = t; i < RB * KIN; i += 128) {
        int r = i / KIN, f = i % KIN;
        int row = row0 + r;
        float v = 0.f;
        if (row < n)
            v = (f < ATTR_W) ? attr[row * ATTR_W + f]
                             : state[row * STATE_W + (f - ATTR_W)];
        s_in[r][f] = v;
    }
    __syncthreads();

    float acc[RB];
#pragma unroll
    for (int r = 0; r < RB; r++) acc[r] = b1[t];
#pragma unroll 4
    for (int k = 0; k < KIN; k++) {
        float w = w1[k * NF + t];
#pragma unroll
        for (int r = 0; r < RB; r++) acc[r] = fmaf(s_in[r][k], w, acc[r]);
    }
#pragma unroll
    for (int r = 0; r < RB; r++) s_h1[r][t] = fmaxf(acc[r], 0.f);
    __syncthreads();

#pragma unroll
    for (int r = 0; r < RB; r++) acc[r] = b2[t];
#pragma unroll 4
    for (int k = 0; k < NF; k++) {
        float w = w2[k * NF + t];
#pragma unroll
        for (int r = 0; r < RB; r++) acc[r] = fmaf(s_h1[r][k], w, acc[r]);
    }
#pragma unroll
    for (int r = 0; r < RB; r++) {
        int row = row0 + r;
        if (row < n) pe[row * NF + t] = fmaxf(acc[r], 0.f);
    }
}

// ---------------------------------------------------------------------------
// Edge encoder: 3-layer MLP over gathered per-edge features (60 -> 128^3)
// ---------------------------------------------------------------------------
__global__ __launch_bounds__(128) void k_edge_enc(
    const float* __restrict__ attr, const float* __restrict__ state,
    const float* __restrict__ Ra,
    const int* __restrict__ recv, const int* __restrict__ send,
    const float* __restrict__ w1, const float* __restrict__ b1,
    const float* __restrict__ w2, const float* __restrict__ b2,
    const float* __restrict__ w3, const float* __restrict__ b3,
    float* __restrict__ ee, int e_cnt)
{
    const int RB = 8;
    const int KIN = 2 * ATTR_W + 2 * STATE_W + REL_W; // 60
    __shared__ float s_in[RB][KIN];
    __shared__ float s_h1[RB][NF];
    __shared__ float s_h2[RB][NF];
    __shared__ int s_r[RB], s_s[RB];

    int e0 = blockIdx.x * RB;
    int t = threadIdx.x;

    if (t < RB) {
        int e = e0 + t;
        s_r[t] = (e < e_cnt) ? recv[e] : 0;
        s_s[t] = (e < e_cnt) ? send[e] : 0;
    }
    __syncthreads();

    for (int i = t; i < RB * KIN; i += 128) {
        int r = i / KIN, f = i % KIN;
        int e = e0 + r;
        int rv = s_r[r], sv = s_s[r];
        float v;
        if (f < 16)       v = attr[rv * ATTR_W + f];
        else if (f < 32)  v = attr[sv * ATTR_W + (f - 16)];
        else if (f < 44)  v = state[rv * STATE_W + (f - 32)];
        else if (f < 56)  v = state[sv * STATE_W + (f - 44)];
        else              v = (e < e_cnt) ? Ra[e * REL_W + (f - 56)] : 0.f;
        s_in[r][f] = v;
    }
    __syncthreads();

    float acc[RB];
#pragma unroll
    for (int r = 0; r < RB; r++) acc[r] = b1[t];
#pragma unroll 4
    for (int k = 0; k < KIN; k++) {
        float w = w1[k * NF + t];
#pragma unroll
        for (int r = 0; r < RB; r++) acc[r] = fmaf(s_in[r][k], w, acc[r]);
    }
#pragma unroll
    for (int r = 0; r < RB; r++) s_h1[r][t] = fmaxf(acc[r], 0.f);
    __syncthreads();

#pragma unroll
    for (int r = 0; r < RB; r++) acc[r] = b2[t];
#pragma unroll 4
    for (int k = 0; k < NF; k++) {
        float w = w2[k * NF + t];
#pragma unroll
        for (int r = 0; r < RB; r++) acc[r] = fmaf(s_h1[r][k], w, acc[r]);
    }
#pragma unroll
    for (int r = 0; r < RB; r++) s_h2[r][t] = fmaxf(acc[r], 0.f);
    __syncthreads();

#pragma unroll
    for (int r = 0; r < RB; r++) acc[r] = b3[t];
#pragma unroll 4
    for (int k = 0; k < NF; k++) {
        float w = w3[k * NF + t];
#pragma unroll
        for (int r = 0; r < RB; r++) acc[r] = fmaf(s_h2[r][k], w, acc[r]);
    }
#pragma unroll
    for (int r = 0; r < RB; r++) {
        int e = e0 + r;
        if (e < e_cnt) ee[e * NF + t] = fmaxf(acc[r], 0.f);
    }
}

// ---------------------------------------------------------------------------
// Relation propagator + fused segment_sum:
// effect_rel = relu([ee, eff[recv], eff[send]] @ rp_w + rp_b); atomicAdd -> agg[recv]
// ---------------------------------------------------------------------------
__global__ __launch_bounds__(128) void k_rel_prop(
    const float* __restrict__ ee, const float* __restrict__ eff,
    const int* __restrict__ recv, const int* __restrict__ send,
    const float* __restrict__ w, const float* __restrict__ b,
    float* __restrict__ agg, int e_cnt)
{
    const int RB = 16;
    const int KIN = 3 * NF; // 384
    __shared__ float s_in[RB][KIN];
    __shared__ int s_r[RB], s_s[RB];

    int e0 = blockIdx.x * RB;
    int t = threadIdx.x;

    if (t < RB) {
        int e = e0 + t;
        s_r[t] = (e < e_cnt) ? recv[e] : 0;
        s_s[t] = (e < e_cnt) ? send[e] : 0;
    }
    __syncthreads();

#pragma unroll
    for (int r = 0; r < RB; r++) {
        int e = e0 + r;
        s_in[r][t]          = (e < e_cnt) ? ee[(long long)e * NF + t] : 0.f;
        s_in[r][NF + t]     = eff[s_r[r] * NF + t];
        s_in[r][2 * NF + t] = eff[s_s[r] * NF + t];
    }
    __syncthreads();

    float acc[RB];
#pragma unroll
    for (int r = 0; r < RB; r++) acc[r] = b[t];
#pragma unroll 4
    for (int k = 0; k < KIN; k++) {
        float wv = w[k * NF + t];
#pragma unroll
        for (int r = 0; r < RB; r++) acc[r] = fmaf(s_in[r][k], wv, acc[r]);
    }
#pragma unroll
    for (int r = 0; r < RB; r++) {
        int e = e0 + r;
        if (e < e_cnt)
            atomicAdd(&agg[s_r[r] * NF + t], fmaxf(acc[r], 0.f));
    }
}

// ---------------------------------------------------------------------------
// Particle propagator: eff = relu([pe, agg] @ pp_w + pp_b)
// ---------------------------------------------------------------------------
__global__ __launch_bounds__(128) void k_part_prop(
    const float* __restrict__ pe, const float* __restrict__ agg,
    const float* __restrict__ w, const float* __restrict__ b,
    float* __restrict__ eff, int n)
{
    const int RB = 8;
    const int KIN = 2 * NF; // 256
    __shared__ float s_in[RB][KIN];

    int row0 = blockIdx.x * RB;
    int t = threadIdx.x;

#pragma unroll
    for (int r = 0; r < RB; r++) {
        int row = row0 + r;
        s_in[r][t]      = (row < n) ? pe [row * NF + t] : 0.f;
        s_in[r][NF + t] = (row < n) ? agg[row * NF + t] : 0.f;
    }
    __syncthreads();

    float acc[RB];
#pragma unroll
    for (int r = 0; r < RB; r++) acc[r] = b[t];
#pragma unroll 4
    for (int k = 0; k < KIN; k++) {
        float wv = w[k * NF + t];
#pragma unroll
        for (int r = 0; r < RB; r++) acc[r] = fmaf(s_in[r][k], wv, acc[r]);
    }
#pragma unroll
    for (int r = 0; r < RB; r++) {
        int row = row0 + r;
        if (row < n) eff[row * NF + t] = fmaxf(acc[r], 0.f);
    }
}

// ---------------------------------------------------------------------------
// Decoder: out = relu(relu(eff@w1+b1)@w2+b2) @ w3 + b3  ([N,3])
// ---------------------------------------------------------------------------
__global__ __launch_bounds__(128) void k_decoder(
    const float* __restrict__ eff,
    const float* __restrict__ w1, const float* __restrict__ b1,
    const float* __restrict__ w2, const float* __restrict__ b2,
    const float* __restrict__ w3, const float* __restrict__ b3,
    float* __restrict__ out, int n)
{
    const int RB = 8;
    __shared__ float s_in[RB][NF];
    __shared__ float s_h1[RB][NF];
    __shared__ float s_h2[RB][NF];

    int row0 = blockIdx.x * RB;
    int t = threadIdx.x;

#pragma unroll
    for (int r = 0; r < RB; r++) {
        int row = row0 + r;
        s_in[r][t] = (row < n) ? eff[row * NF + t] : 0.f;
    }
    __syncthreads();

    float acc[RB];
#pragma unroll
    for (int r = 0; r < RB; r++) acc[r] = b1[t];
#pragma unroll 4
    for (int k = 0; k < NF; k++) {
        float w = w1[k * NF + t];
#pragma unroll
        for (int r = 0; r < RB; r++) acc[r] = fmaf(s_in[r][k], w, acc[r]);
    }
#pragma unroll
    for (int r = 0; r < RB; r++) s_h1[r][t] = fmaxf(acc[r], 0.f);
    __syncthreads();

#pragma unroll
    for (int r = 0; r < RB; r++) acc[r] = b2[t];
#pragma unroll 4
    for (int k = 0; k < NF; k++) {
        float w = w2[k * NF + t];
#pragma unroll
        for (int r = 0; r < RB; r++) acc[r] = fmaf(s_h1[r][k], w, acc[r]);
    }
#pragma unroll
    for (int r = 0; r < RB; r++) s_h2[r][t] = fmaxf(acc[r], 0.f);
    __syncthreads();

    // Final 128 -> 3 projection: 24 dot products handled by threads 0..23
    if (t < RB * 3) {
        int r = t / 3, j = t % 3;
        int row = row0 + r;
        if (row < n) {
            float a = b3[j];
#pragma unroll 4
            for (int k = 0; k < NF; k++)
                a = fmaf(s_h2[r][k], w3[k * 3 + j], a);
            out[row * 3 + j] = a;
        }
    }
}

// ---------------------------------------------------------------------------
// launch
// ---------------------------------------------------------------------------
extern "C" void kernel_launch(void* const* d_in, const int* in_sizes, int n_in,
                              void* d_out, int out_size)
{
    const float* attr  = (const float*)d_in[0];
    const float* state = (const float*)d_in[1];
    const float* Ra    = (const float*)d_in[2];
    const int*   recv  = (const int*)  d_in[3];
    const int*   send  = (const int*)  d_in[4];
    // d_in[5] = pstep (device scalar; fixed to 2 for this problem)
    const float* pe_w1 = (const float*)d_in[6];
    const float* pe_b1 = (const float*)d_in[7];
    const float* pe_w2 = (const float*)d_in[8];
    const float* pe_b2 = (const float*)d_in[9];
    const float* ee_w1 = (const float*)d_in[10];
    const float* ee_b1 = (const float*)d_in[11];
    const float* ee_w2 = (const float*)d_in[12];
    const float* ee_b2 = (const float*)d_in[13];
    const float* ee_w3 = (const float*)d_in[14];
    const float* ee_b3 = (const float*)d_in[15];
    const float* rp_w  = (const float*)d_in[16];
    const float* rp_b  = (const float*)d_in[17];
    const float* pp_w  = (const float*)d_in[18];
    const float* pp_b  = (const float*)d_in[19];
    const float* de_w1 = (const float*)d_in[20];
    const float* de_b1 = (const float*)d_in[21];
    const float* de_w2 = (const float*)d_in[22];
    const float* de_b2 = (const float*)d_in[23];
    const float* de_w3 = (const float*)d_in[24];
    const float* de_b3 = (const float*)d_in[25];

    const int n = in_sizes[0] / ATTR_W;   // 100000
    const int e = in_sizes[2] / REL_W;    // 500000

    float *pe, *ee, *eff, *agg;
    cudaGetSymbolAddress((void**)&pe,  g_pe);
    cudaGetSymbolAddress((void**)&ee,  g_ee);
    cudaGetSymbolAddress((void**)&eff, g_eff);
    cudaGetSymbolAddress((void**)&agg, g_agg);

    const int RB_N = 8, RB_E8 = 8, RB_E16 = 16;
    dim3 blk(128);

    // effect starts at zero
    k_zero<<<1024, 256>>>(eff, n * NF);

    // encoders
    k_node_enc<<<(n + RB_N - 1) / RB_N, blk>>>(attr, state, pe_w1, pe_b1, pe_w2, pe_b2, pe, n);
    k_edge_enc<<<(e + RB_E8 - 1) / RB_E8, blk>>>(attr, state, Ra, recv, send,
                                                 ee_w1, ee_b1, ee_w2, ee_b2, ee_w3, ee_b3, ee, e);

    // propagation (pstep = 2)
    for (int ps = 0; ps < PSTEP; ps++) {
        k_zero<<<1024, 256>>>(agg, n * NF);
        k_rel_prop<<<(e + RB_E16 - 1) / RB_E16, blk>>>(ee, eff, recv, send, rp_w, rp_b, agg, e);
        k_part_prop<<<(n + RB_N - 1) / RB_N, blk>>>(pe, agg, pp_w, pp_b, eff, n);
    }

    // decoder
    k_decoder<<<(n + RB_N - 1) / RB_N, blk>>>(eff, de_w1, de_b1, de_w2, de_b2, de_w3, de_b3,
                                              (float*)d_out, n);
}

// round 3
// speedup vs baseline: 1.6180x; 1.6180x over previous
#include <cuda_runtime.h>
#include <cuda_bf16.h>
#include <cstdint>

// Problem constants (fixed by the dataset)
#define NN 100000
#define EE 500000
#define NF 128
#define ATTR_W 16
#define STATE_W 12
#define REL_W 4
#define PSTEP 2

// Scratch (device globals; no runtime allocation allowed)
__device__ float g_pe [NN * NF];   // particle encoding   [N,128]
__device__ float g_ee [EE * NF];   // edge encoding       [E,128]
__device__ float g_eff[NN * NF];   // particle effect     [N,128]
__device__ float g_agg[NN * NF];   // segment-sum target  [N,128]

// ---------------------------------------------------------------------------
// helpers
// ---------------------------------------------------------------------------
__device__ __forceinline__ uint32_t cvt_tf32(float x) {
    uint32_t r;
    asm("cvt.rna.tf32.f32 %0, %1;" : "=r"(r) : "f"(x));
    return r;
}

// m16n8k8 tf32 MMA (row.col), fp32 accumulate in-place
__device__ __forceinline__ void mma_tf32(float* c, const uint32_t* a, const uint32_t* b) {
    asm volatile(
        "mma.sync.aligned.m16n8k8.row.col.f32.tf32.tf32.f32 "
        "{%0,%1,%2,%3}, {%4,%5,%6,%7}, {%8,%9}, {%0,%1,%2,%3};"
        : "+f"(c[0]), "+f"(c[1]), "+f"(c[2]), "+f"(c[3])
        : "r"(a[0]), "r"(a[1]), "r"(a[2]), "r"(a[3]), "r"(b[0]), "r"(b[1]));
}

// ---------------------------------------------------------------------------
// zero kernel
// ---------------------------------------------------------------------------
__global__ void k_zero(float* p, int n) {
    int i = blockIdx.x * blockDim.x + threadIdx.x;
    int stride = gridDim.x * blockDim.x;
    for (; i < n; i += stride) p[i] = 0.0f;
}

// ---------------------------------------------------------------------------
// Node encoder: pe = relu(relu([attr,state] @ w1 + b1) @ w2 + b2)
// ---------------------------------------------------------------------------
__global__ __launch_bounds__(128) void k_node_enc(
    const float* __restrict__ attr, const float* __restrict__ state,
    const float* __restrict__ w1, const float* __restrict__ b1,
    const float* __restrict__ w2, const float* __restrict__ b2,
    float* __restrict__ pe, int n)
{
    const int RB = 8;
    const int KIN = ATTR_W + STATE_W; // 28
    __shared__ float s_in[RB][KIN];
    __shared__ float s_h1[RB][NF];

    int row0 = blockIdx.x * RB;
    int t = threadIdx.x;

    for (int i = t; i < RB * KIN; i += 128) {
        int r = i / KIN, f = i % KIN;
        int row = row0 + r;
        float v = 0.f;
        if (row < n)
            v = (f < ATTR_W) ? attr[row * ATTR_W + f]
                             : state[row * STATE_W + (f - ATTR_W)];
        s_in[r][f] = v;
    }
    __syncthreads();

    float acc[RB];
#pragma unroll
    for (int r = 0; r < RB; r++) acc[r] = b1[t];
#pragma unroll 4
    for (int k = 0; k < KIN; k++) {
        float w = w1[k * NF + t];
#pragma unroll
        for (int r = 0; r < RB; r++) acc[r] = fmaf(s_in[r][k], w, acc[r]);
    }
#pragma unroll
    for (int r = 0; r < RB; r++) s_h1[r][t] = fmaxf(acc[r], 0.f);
    __syncthreads();

#pragma unroll
    for (int r = 0; r < RB; r++) acc[r] = b2[t];
#pragma unroll 4
    for (int k = 0; k < NF; k++) {
        float w = w2[k * NF + t];
#pragma unroll
        for (int r = 0; r < RB; r++) acc[r] = fmaf(s_h1[r][k], w, acc[r]);
    }
#pragma unroll
    for (int r = 0; r < RB; r++) {
        int row = row0 + r;
        if (row < n) pe[row * NF + t] = fmaxf(acc[r], 0.f);
    }
}

// ---------------------------------------------------------------------------
// Edge encoder: 3-layer MLP over gathered per-edge features (60 -> 128^3)
// ---------------------------------------------------------------------------
__global__ __launch_bounds__(128) void k_edge_enc(
    const float* __restrict__ attr, const float* __restrict__ state,
    const float* __restrict__ Ra,
    const int* __restrict__ recv, const int* __restrict__ send,
    const float* __restrict__ w1, const float* __restrict__ b1,
    const float* __restrict__ w2, const float* __restrict__ b2,
    const float* __restrict__ w3, const float* __restrict__ b3,
    float* __restrict__ ee, int e_cnt)
{
    const int RB = 8;
    const int KIN = 2 * ATTR_W + 2 * STATE_W + REL_W; // 60
    __shared__ float s_in[RB][KIN];
    __shared__ float s_h1[RB][NF];
    __shared__ float s_h2[RB][NF];
    __shared__ int s_r[RB], s_s[RB];

    int e0 = blockIdx.x * RB;
    int t = threadIdx.x;

    if (t < RB) {
        int e = e0 + t;
        s_r[t] = (e < e_cnt) ? recv[e] : 0;
        s_s[t] = (e < e_cnt) ? send[e] : 0;
    }
    __syncthreads();

    for (int i = t; i < RB * KIN; i += 128) {
        int r = i / KIN, f = i % KIN;
        int e = e0 + r;
        int rv = s_r[r], sv = s_s[r];
        float v;
        if (f < 16)       v = attr[rv * ATTR_W + f];
        else if (f < 32)  v = attr[sv * ATTR_W + (f - 16)];
        else if (f < 44)  v = state[rv * STATE_W + (f - 32)];
        else if (f < 56)  v = state[sv * STATE_W + (f - 44)];
        else              v = (e < e_cnt) ? Ra[e * REL_W + (f - 56)] : 0.f;
        s_in[r][f] = v;
    }
    __syncthreads();

    float acc[RB];
#pragma unroll
    for (int r = 0; r < RB; r++) acc[r] = b1[t];
#pragma unroll 4
    for (int k = 0; k < KIN; k++) {
        float w = w1[k * NF + t];
#pragma unroll
        for (int r = 0; r < RB; r++) acc[r] = fmaf(s_in[r][k], w, acc[r]);
    }
#pragma unroll
    for (int r = 0; r < RB; r++) s_h1[r][t] = fmaxf(acc[r], 0.f);
    __syncthreads();

#pragma unroll
    for (int r = 0; r < RB; r++) acc[r] = b2[t];
#pragma unroll 4
    for (int k = 0; k < NF; k++) {
        float w = w2[k * NF + t];
#pragma unroll
        for (int r = 0; r < RB; r++) acc[r] = fmaf(s_h1[r][k], w, acc[r]);
    }
#pragma unroll
    for (int r = 0; r < RB; r++) s_h2[r][t] = fmaxf(acc[r], 0.f);
    __syncthreads();

#pragma unroll
    for (int r = 0; r < RB; r++) acc[r] = b3[t];
#pragma unroll 4
    for (int k = 0; k < NF; k++) {
        float w = w3[k * NF + t];
#pragma unroll
        for (int r = 0; r < RB; r++) acc[r] = fmaf(s_h2[r][k], w, acc[r]);
    }
#pragma unroll
    for (int r = 0; r < RB; r++) {
        int e = e0 + r;
        if (e < e_cnt) ee[e * NF + t] = fmaxf(acc[r], 0.f);
    }
}

// ---------------------------------------------------------------------------
// Relation propagator via mma.sync tf32 + fused segment_sum.
//   A[128 edges, 384] = [ee | eff[recv] | eff[send]]  (gathered tf32, smem chunked)
//   B[384, 128] = rp_w                                 (tf32, staged once per CTA)
//   C = A @ B (fp32 frags), epilogue: +bias, relu, atomicAdd -> agg[recv]
// Persistent: 148 CTAs x 256 threads (8 warps = 4(m) x 2(n)).
// Strides: A pad 36 (==4 mod 32), B pad 136 (==8 mod 32) -> conflict-free LDS.
// ---------------------------------------------------------------------------
#define A_STRIDE 36
#define B_STRIDE 136
#define OFF_RECV 0
#define OFF_SEND 512
#define OFF_BIAS 1024
#define OFF_A    1536                        // 128*36*4   = 18432
#define OFF_B    (OFF_A + 128 * A_STRIDE * 4)// 19968
#define RP_SMEM_BYTES (OFF_B + 384 * B_STRIDE * 4)  // 19968 + 208896 = 228864

__global__ __launch_bounds__(256, 1) void k_rel_prop_mma(
    const float* __restrict__ ee, const float* __restrict__ eff,
    const int* __restrict__ recv, const int* __restrict__ send,
    const float* __restrict__ w, const float* __restrict__ b,
    float* __restrict__ agg, int e_cnt)
{
    extern __shared__ char smem[];
    int*      s_recv = (int*)     (smem + OFF_RECV);
    int*      s_send = (int*)     (smem + OFF_SEND);
    float*    s_bias = (float*)   (smem + OFF_BIAS);
    uint32_t* As     = (uint32_t*)(smem + OFF_A);
    uint32_t* Bs     = (uint32_t*)(smem + OFF_B);

    const int tid = threadIdx.x;
    const int wid = tid >> 5;
    const int lane = tid & 31;
    const int grp = lane >> 2;      // 0..7
    const int tg  = lane & 3;       // 0..3
    const int wm  = wid & 3;        // warp m index: rows [wm*32, wm*32+32)
    const int wn  = wid >> 2;       // warp n index: cols [wn*64, wn*64+64)

    // Stage B (rp_w, tf32) once per CTA
    for (int idx = tid; idx < 384 * 128; idx += 256) {
        int k = idx >> 7, n = idx & 127;
        Bs[k * B_STRIDE + n] = cvt_tf32(w[k * NF + n]);
    }
    if (tid < 128) s_bias[tid] = b[tid];
    __syncthreads();

    const int ntiles = (e_cnt + 127) >> 7;
    const int r_st   = tid >> 1;    // staging row 0..127
    const int half   = tid & 1;

    for (int tile = blockIdx.x; tile < ntiles; tile += gridDim.x) {
        const int e0 = tile << 7;
        if (tid < 128) {
            int e = e0 + tid;
            s_recv[tid] = (e < e_cnt) ? recv[e] : 0;
            s_send[tid] = (e < e_cnt) ? send[e] : 0;
        }

        float acc[2][8][4];
#pragma unroll
        for (int mt = 0; mt < 2; mt++)
#pragma unroll
            for (int nt = 0; nt < 8; nt++)
#pragma unroll
                for (int i = 0; i < 4; i++) acc[mt][nt][i] = 0.f;

        __syncthreads();

        for (int c = 0; c < 12; c++) {
            // ---- stage A chunk c: [128 rows x 32 k] tf32 ----
            const float* src;
            bool valid = true;
            if (c < 4) {
                int e = e0 + r_st;
                valid = (e < e_cnt);
                src = ee + (size_t)e * NF + c * 32;
            } else if (c < 8) {
                src = eff + (size_t)s_recv[r_st] * NF + (c - 4) * 32;
            } else {
                src = eff + (size_t)s_send[r_st] * NF + (c - 8) * 32;
            }
            uint32_t* dst = As + r_st * A_STRIDE + half * 16;
#pragma unroll
            for (int q = 0; q < 4; q++) {
                float4 v = valid ? *(const float4*)(src + half * 16 + q * 4)
                                 : make_float4(0.f, 0.f, 0.f, 0.f);
                uint4 u;
                u.x = cvt_tf32(v.x); u.y = cvt_tf32(v.y);
                u.z = cvt_tf32(v.z); u.w = cvt_tf32(v.w);
                *(uint4*)(dst + q * 4) = u;
            }
            __syncthreads();

            // ---- 4 k8-steps over this chunk ----
#pragma unroll
            for (int s = 0; s < 4; s++) {
                const int kk = c * 32 + s * 8;      // global k of this step
                const int ac = s * 8;               // col within A chunk

                uint32_t bf[8][2];
#pragma unroll
                for (int nt = 0; nt < 8; nt++) {
                    int n = wn * 64 + nt * 8 + grp;
                    bf[nt][0] = Bs[(kk + tg)     * B_STRIDE + n];
                    bf[nt][1] = Bs[(kk + tg + 4) * B_STRIDE + n];
                }
#pragma unroll
                for (int mt = 0; mt < 2; mt++) {
                    int rb = wm * 32 + mt * 16;
                    uint32_t af[4];
                    af[0] = As[(rb + grp)     * A_STRIDE + ac + tg];
                    af[1] = As[(rb + grp + 8) * A_STRIDE + ac + tg];
                    af[2] = As[(rb + grp)     * A_STRIDE + ac + tg + 4];
                    af[3] = As[(rb + grp + 8) * A_STRIDE + ac + tg + 4];
#pragma unroll
                    for (int nt = 0; nt < 8; nt++)
                        mma_tf32(acc[mt][nt], af, bf[nt]);
                }
            }
            __syncthreads();   // As reused next chunk
        }

        // ---- epilogue: bias + relu + atomicAdd scatter to agg[recv] ----
#pragma unroll
        for (int mt = 0; mt < 2; mt++) {
            int r_lo = wm * 32 + mt * 16 + grp;
            int r_hi = r_lo + 8;
            bool v_lo = (e0 + r_lo) < e_cnt;
            bool v_hi = (e0 + r_hi) < e_cnt;
            int d_lo = s_recv[r_lo];
            int d_hi = s_recv[r_hi];
#pragma unroll
            for (int nt = 0; nt < 8; nt++) {
                int col = wn * 64 + nt * 8 + tg * 2;
                float b0 = s_bias[col], b1 = s_bias[col + 1];
                if (v_lo) {
                    atomicAdd(&agg[(size_t)d_lo * NF + col],     fmaxf(acc[mt][nt][0] + b0, 0.f));
                    atomicAdd(&agg[(size_t)d_lo * NF + col + 1], fmaxf(acc[mt][nt][1] + b1, 0.f));
                }
                if (v_hi) {
                    atomicAdd(&agg[(size_t)d_hi * NF + col],     fmaxf(acc[mt][nt][2] + b0, 0.f));
                    atomicAdd(&agg[(size_t)d_hi * NF + col + 1], fmaxf(acc[mt][nt][3] + b1, 0.f));
                }
            }
        }
        __syncthreads();  // s_recv reused next tile
    }
}

// ---------------------------------------------------------------------------
// Particle propagator: eff = relu([pe, agg] @ pp_w + pp_b)
// ---------------------------------------------------------------------------
__global__ __launch_bounds__(128) void k_part_prop(
    const float* __restrict__ pe, const float* __restrict__ agg,
    const float* __restrict__ w, const float* __restrict__ b,
    float* __restrict__ eff, int n)
{
    const int RB = 8;
    const int KIN = 2 * NF; // 256
    __shared__ float s_in[RB][KIN];

    int row0 = blockIdx.x * RB;
    int t = threadIdx.x;

#pragma unroll
    for (int r = 0; r < RB; r++) {
        int row = row0 + r;
        s_in[r][t]      = (row < n) ? pe [row * NF + t] : 0.f;
        s_in[r][NF + t] = (row < n) ? agg[row * NF + t] : 0.f;
    }
    __syncthreads();

    float acc[RB];
#pragma unroll
    for (int r = 0; r < RB; r++) acc[r] = b[t];
#pragma unroll 4
    for (int k = 0; k < KIN; k++) {
        float wv = w[k * NF + t];
#pragma unroll
        for (int r = 0; r < RB; r++) acc[r] = fmaf(s_in[r][k], wv, acc[r]);
    }
#pragma unroll
    for (int r = 0; r < RB; r++) {
        int row = row0 + r;
        if (row < n) eff[row * NF + t] = fmaxf(acc[r], 0.f);
    }
}

// ---------------------------------------------------------------------------
// Decoder: out = relu(relu(eff@w1+b1)@w2+b2) @ w3 + b3  ([N,3])
// ---------------------------------------------------------------------------
__global__ __launch_bounds__(128) void k_decoder(
    const float* __restrict__ eff,
    const float* __restrict__ w1, const float* __restrict__ b1,
    const float* __restrict__ w2, const float* __restrict__ b2,
    const float* __restrict__ w3, const float* __restrict__ b3,
    float* __restrict__ out, int n)
{
    const int RB = 8;
    __shared__ float s_in[RB][NF];
    __shared__ float s_h1[RB][NF];
    __shared__ float s_h2[RB][NF];

    int row0 = blockIdx.x * RB;
    int t = threadIdx.x;

#pragma unroll
    for (int r = 0; r < RB; r++) {
        int row = row0 + r;
        s_in[r][t] = (row < n) ? eff[row * NF + t] : 0.f;
    }
    __syncthreads();

    float acc[RB];
#pragma unroll
    for (int r = 0; r < RB; r++) acc[r] = b1[t];
#pragma unroll 4
    for (int k = 0; k < NF; k++) {
        float w = w1[k * NF + t];
#pragma unroll
        for (int r = 0; r < RB; r++) acc[r] = fmaf(s_in[r][k], w, acc[r]);
    }
#pragma unroll
    for (int r = 0; r < RB; r++) s_h1[r][t] = fmaxf(acc[r], 0.f);
    __syncthreads();

#pragma unroll
    for (int r = 0; r < RB; r++) acc[r] = b2[t];
#pragma unroll 4
    for (int k = 0; k < NF; k++) {
        float w = w2[k * NF + t];
#pragma unroll
        for (int r = 0; r < RB; r++) acc[r] = fmaf(s_h1[r][k], w, acc[r]);
    }
#pragma unroll
    for (int r = 0; r < RB; r++) s_h2[r][t] = fmaxf(acc[r], 0.f);
    __syncthreads();

    if (t < RB * 3) {
        int r = t / 3, j = t % 3;
        int row = row0 + r;
        if (row < n) {
            float a = b3[j];
#pragma unroll 4
            for (int k = 0; k < NF; k++)
                a = fmaf(s_h2[r][k], w3[k * 3 + j], a);
            out[row * 3 + j] = a;
        }
    }
}

// ---------------------------------------------------------------------------
// launch
// ---------------------------------------------------------------------------
extern "C" void kernel_launch(void* const* d_in, const int* in_sizes, int n_in,
                              void* d_out, int out_size)
{
    const float* attr  = (const float*)d_in[0];
    const float* state = (const float*)d_in[1];
    const float* Ra    = (const float*)d_in[2];
    const int*   recv  = (const int*)  d_in[3];
    const int*   send  = (const int*)  d_in[4];
    // d_in[5] = pstep (device scalar; fixed to 2 for this problem)
    const float* pe_w1 = (const float*)d_in[6];
    const float* pe_b1 = (const float*)d_in[7];
    const float* pe_w2 = (const float*)d_in[8];
    const float* pe_b2 = (const float*)d_in[9];
    const float* ee_w1 = (const float*)d_in[10];
    const float* ee_b1 = (const float*)d_in[11];
    const float* ee_w2 = (const float*)d_in[12];
    const float* ee_b2 = (const float*)d_in[13];
    const float* ee_w3 = (const float*)d_in[14];
    const float* ee_b3 = (const float*)d_in[15];
    const float* rp_w  = (const float*)d_in[16];
    const float* rp_b  = (const float*)d_in[17];
    const float* pp_w  = (const float*)d_in[18];
    const float* pp_b  = (const float*)d_in[19];
    const float* de_w1 = (const float*)d_in[20];
    const float* de_b1 = (const float*)d_in[21];
    const float* de_w2 = (const float*)d_in[22];
    const float* de_b2 = (const float*)d_in[23];
    const float* de_w3 = (const float*)d_in[24];
    const float* de_b3 = (const float*)d_in[25];

    const int n = in_sizes[0] / ATTR_W;   // 100000
    const int e = in_sizes[2] / REL_W;    // 500000

    float *pe, *ee, *eff, *agg;
    cudaGetSymbolAddress((void**)&pe,  g_pe);
    cudaGetSymbolAddress((void**)&ee,  g_ee);
    cudaGetSymbolAddress((void**)&eff, g_eff);
    cudaGetSymbolAddress((void**)&agg, g_agg);

    cudaFuncSetAttribute(k_rel_prop_mma,
                         cudaFuncAttributeMaxDynamicSharedMemorySize, RP_SMEM_BYTES);

    const int RB_N = 8, RB_E8 = 8;
    dim3 blk(128);

    // effect starts at zero
    k_zero<<<1024, 256>>>(eff, n * NF);

    // encoders
    k_node_enc<<<(n + RB_N - 1) / RB_N, blk>>>(attr, state, pe_w1, pe_b1, pe_w2, pe_b2, pe, n);
    k_edge_enc<<<(e + RB_E8 - 1) / RB_E8, blk>>>(attr, state, Ra, recv, send,
                                                 ee_w1, ee_b1, ee_w2, ee_b2, ee_w3, ee_b3, ee, e);

    // propagation (pstep = 2)
    for (int ps = 0; ps < PSTEP; ps++) {
        k_zero<<<1024, 256>>>(agg, n * NF);
        k_rel_prop_mma<<<148, 256, RP_SMEM_BYTES>>>(ee, eff, recv, send, rp_w, rp_b, agg, e);
        k_part_prop<<<(n + RB_N - 1) / RB_N, blk>>>(pe, agg, pp_w, pp_b, eff, n);
    }

    // decoder
    k_decoder<<<(n + RB_N - 1) / RB_N, blk>>>(eff, de_w1, de_b1, de_w2, de_b2, de_w3, de_b3,
                                              (float*)d_out, n);
}

// round 4
// speedup vs baseline: 2.3531x; 1.4543x over previous
#include <cuda_runtime.h>
#include <cuda_bf16.h>
#include <cstdint>

// Problem constants (fixed by the dataset)
#define NN 100000
#define EE 500000
#define NF 128
#define ATTR_W 16
#define STATE_W 12
#define REL_W 4
#define PSTEP 2

// Scratch (device globals; no runtime allocation allowed)
__device__ float g_pe [NN * NF];   // particle encoding   [N,128]
__device__ float g_ee [EE * NF];   // edge encoding       [E,128]
__device__ float g_eff[NN * NF];   // particle effect     [N,128]
__device__ float g_agg[NN * NF];   // segment-sum target  [N,128]

// ---------------------------------------------------------------------------
// helpers
// ---------------------------------------------------------------------------
__device__ __forceinline__ uint32_t cvt_tf32(float x) {
    uint32_t r;
    asm("cvt.rna.tf32.f32 %0, %1;" : "=r"(r) : "f"(x));
    return r;
}

// m16n8k8 tf32 MMA (row.col), fp32 accumulate in-place
__device__ __forceinline__ void mma_tf32(float* c, const uint32_t* a, const uint32_t* b) {
    asm volatile(
        "mma.sync.aligned.m16n8k8.row.col.f32.tf32.tf32.f32 "
        "{%0,%1,%2,%3}, {%4,%5,%6,%7}, {%8,%9}, {%0,%1,%2,%3};"
        : "+f"(c[0]), "+f"(c[1]), "+f"(c[2]), "+f"(c[3])
        : "r"(a[0]), "r"(a[1]), "r"(a[2]), "r"(a[3]), "r"(b[0]), "r"(b[1]));
}

// weight swizzle: [K x 128], addr = k*128 + (n ^ ((k&3)<<3))
#define WSW(k, n) (((k) << 7) + ((n) ^ (((k) & 3) << 3)))
// activation swizzle: [128 x 128], addr = row*128 + (col ^ ((row&7)<<2))
#define ASW(r, c) (((r) << 7) + ((c) ^ (((r) & 7) << 2)))

// ---------------------------------------------------------------------------
// zero kernel
// ---------------------------------------------------------------------------
__global__ void k_zero(float* p, int n) {
    int i = blockIdx.x * blockDim.x + threadIdx.x;
    int stride = gridDim.x * blockDim.x;
    for (; i < n; i += stride) p[i] = 0.0f;
}

// ---------------------------------------------------------------------------
// Node encoder: pe = relu(relu([attr,state] @ w1 + b1) @ w2 + b2)
// ---------------------------------------------------------------------------
__global__ __launch_bounds__(128) void k_node_enc(
    const float* __restrict__ attr, const float* __restrict__ state,
    const float* __restrict__ w1, const float* __restrict__ b1,
    const float* __restrict__ w2, const float* __restrict__ b2,
    float* __restrict__ pe, int n)
{
    const int RB = 8;
    const int KIN = ATTR_W + STATE_W; // 28
    __shared__ float s_in[RB][KIN];
    __shared__ float s_h1[RB][NF];

    int row0 = blockIdx.x * RB;
    int t = threadIdx.x;

    for (int i = t; i < RB * KIN; i += 128) {
        int r = i / KIN, f = i % KIN;
        int row = row0 + r;
        float v = 0.f;
        if (row < n)
            v = (f < ATTR_W) ? attr[row * ATTR_W + f]
                             : state[row * STATE_W + (f - ATTR_W)];
        s_in[r][f] = v;
    }
    __syncthreads();

    float acc[RB];
#pragma unroll
    for (int r = 0; r < RB; r++) acc[r] = b1[t];
#pragma unroll 4
    for (int k = 0; k < KIN; k++) {
        float w = w1[k * NF + t];
#pragma unroll
        for (int r = 0; r < RB; r++) acc[r] = fmaf(s_in[r][k], w, acc[r]);
    }
#pragma unroll
    for (int r = 0; r < RB; r++) s_h1[r][t] = fmaxf(acc[r], 0.f);
    __syncthreads();

#pragma unroll
    for (int r = 0; r < RB; r++) acc[r] = b2[t];
#pragma unroll 4
    for (int k = 0; k < NF; k++) {
        float w = w2[k * NF + t];
#pragma unroll
        for (int r = 0; r < RB; r++) acc[r] = fmaf(s_h1[r][k], w, acc[r]);
    }
#pragma unroll
    for (int r = 0; r < RB; r++) {
        int row = row0 + r;
        if (row < n) pe[row * NF + t] = fmaxf(acc[r], 0.f);
    }
}

// ---------------------------------------------------------------------------
// Edge encoder via mma.sync tf32.
//   in[128 edges, 64] = [attr[rv]|attr[sv]|state[rv]|state[sv]|Ra|pad0]
//   3 layers: (64->128), (128->128), (128->128), relu between, fp32 out.
// Weights XOR-swizzled in smem (staged once), act buffer ping-ponged in place.
// Persistent: 148 CTAs x 256 threads (8 warps = 4(m) x 2(n)).
// ---------------------------------------------------------------------------
#define EE_OFF_RECV 0
#define EE_OFF_SEND 512
#define EE_OFF_B1   1024
#define EE_OFF_B2   1536
#define EE_OFF_B3   2048
#define EE_OFF_W1   2560                       // 64*128*4  = 32768
#define EE_OFF_W2   (EE_OFF_W1 + 32768)        // 35328, 128*128*4 = 65536
#define EE_OFF_W3   (EE_OFF_W2 + 65536)        // 100864
#define EE_OFF_ACT  (EE_OFF_W3 + 65536)        // 166400
#define EE_SMEM_BYTES (EE_OFF_ACT + 65536)     // 231936 <= 232448

__global__ __launch_bounds__(256, 1) void k_edge_enc_mma(
    const float* __restrict__ attr, const float* __restrict__ state,
    const float* __restrict__ Ra,
    const int* __restrict__ recv, const int* __restrict__ send,
    const float* __restrict__ w1, const float* __restrict__ b1,
    const float* __restrict__ w2, const float* __restrict__ b2,
    const float* __restrict__ w3, const float* __restrict__ b3,
    float* __restrict__ ee, int e_cnt)
{
    extern __shared__ char smem[];
    int*      s_recv = (int*)     (smem + EE_OFF_RECV);
    int*      s_send = (int*)     (smem + EE_OFF_SEND);
    float*    s_b1   = (float*)   (smem + EE_OFF_B1);
    float*    s_b2   = (float*)   (smem + EE_OFF_B2);
    float*    s_b3   = (float*)   (smem + EE_OFF_B3);
    uint32_t* W1s    = (uint32_t*)(smem + EE_OFF_W1);
    uint32_t* W2s    = (uint32_t*)(smem + EE_OFF_W2);
    uint32_t* W3s    = (uint32_t*)(smem + EE_OFF_W3);
    uint32_t* As     = (uint32_t*)(smem + EE_OFF_ACT);

    const int tid = threadIdx.x;
    const int wid = tid >> 5;
    const int lane = tid & 31;
    const int grp = lane >> 2;   // 0..7
    const int tg  = lane & 3;    // 0..3
    const int wm  = wid & 3;     // rows [wm*32, +32)
    const int wn  = wid >> 2;    // cols [wn*64, +64)

    // ---- stage weights (once per CTA), tf32 + swizzle ----
    for (int idx = tid; idx < 64 * 128; idx += 256) {
        int k = idx >> 7, n = idx & 127;
        float v = (k < 60) ? w1[k * NF + n] : 0.f;
        W1s[WSW(k, n)] = cvt_tf32(v);
    }
    for (int idx = tid; idx < 128 * 128; idx += 256) {
        int k = idx >> 7, n = idx & 127;
        W2s[WSW(k, n)] = cvt_tf32(w2[k * NF + n]);
        W3s[WSW(k, n)] = cvt_tf32(w3[k * NF + n]);
    }
    if (tid < 128) { s_b1[tid] = b1[tid]; s_b2[tid] = b2[tid]; s_b3[tid] = b3[tid]; }

    const int ntiles = (e_cnt + 127) >> 7;
    const int r_st   = tid >> 1;   // staging row 0..127
    const int half   = tid & 1;

    float acc[2][8][4];

    __syncthreads();

    for (int tile = blockIdx.x; tile < ntiles; tile += gridDim.x) {
        const int e0 = tile << 7;
        if (tid < 128) {
            int e = e0 + tid;
            s_recv[tid] = (e < e_cnt) ? recv[e] : 0;
            s_send[tid] = (e < e_cnt) ? send[e] : 0;
        }
        __syncthreads();

        // ---- gather input tile [128 x 64] into As (tf32, swizzled) ----
        {
            int rv = s_recv[r_st], sv = s_send[r_st];
            int e  = e0 + r_st;
            if (half == 0) {
                // cols 0..31: attr[rv](16) | attr[sv](16)
#pragma unroll
                for (int q = 0; q < 4; q++) {
                    float4 v = *(const float4*)(attr + (size_t)rv * ATTR_W + q * 4);
                    uint4 u = { cvt_tf32(v.x), cvt_tf32(v.y), cvt_tf32(v.z), cvt_tf32(v.w) };
                    *(uint4*)(As + ASW(r_st, q * 4)) = u;
                }
#pragma unroll
                for (int q = 0; q < 4; q++) {
                    float4 v = *(const float4*)(attr + (size_t)sv * ATTR_W + q * 4);
                    uint4 u = { cvt_tf32(v.x), cvt_tf32(v.y), cvt_tf32(v.z), cvt_tf32(v.w) };
                    *(uint4*)(As + ASW(r_st, 16 + q * 4)) = u;
                }
            } else {
                // cols 32..63: state[rv](12) | state[sv](12) | Ra(4) | zeros(4)
#pragma unroll
                for (int q = 0; q < 3; q++) {
                    float4 v = *(const float4*)(state + (size_t)rv * STATE_W + q * 4);
                    uint4 u = { cvt_tf32(v.x), cvt_tf32(v.y), cvt_tf32(v.z), cvt_tf32(v.w) };
                    *(uint4*)(As + ASW(r_st, 32 + q * 4)) = u;
                }
#pragma unroll
                for (int q = 0; q < 3; q++) {
                    float4 v = *(const float4*)(state + (size_t)sv * STATE_W + q * 4);
                    uint4 u = { cvt_tf32(v.x), cvt_tf32(v.y), cvt_tf32(v.z), cvt_tf32(v.w) };
                    *(uint4*)(As + ASW(r_st, 44 + q * 4)) = u;
                }
                {
                    float4 v = (e < e_cnt) ? *(const float4*)(Ra + (size_t)e * REL_W)
                                           : make_float4(0.f, 0.f, 0.f, 0.f);
                    uint4 u = { cvt_tf32(v.x), cvt_tf32(v.y), cvt_tf32(v.z), cvt_tf32(v.w) };
                    *(uint4*)(As + ASW(r_st, 56)) = u;
                }
                {
                    uint4 u = { 0u, 0u, 0u, 0u };
                    *(uint4*)(As + ASW(r_st, 60)) = u;
                }
            }
        }
        __syncthreads();

        // =========== layer 1: [128x64] @ w1 -> h1 ===========
#pragma unroll
        for (int mt = 0; mt < 2; mt++)
#pragma unroll
            for (int nt = 0; nt < 8; nt++)
#pragma unroll
                for (int i = 0; i < 4; i++) acc[mt][nt][i] = 0.f;

#pragma unroll
        for (int s = 0; s < 8; s++) {
            const int kk = s * 8;
            uint32_t bf[8][2];
#pragma unroll
            for (int nt = 0; nt < 8; nt++) {
                int n_sw = (wn * 64 + nt * 8 + grp) ^ (tg << 3);
                bf[nt][0] = W1s[((kk + tg) << 7) + n_sw];
                bf[nt][1] = W1s[((kk + tg + 4) << 7) + n_sw];
            }
#pragma unroll
            for (int mt = 0; mt < 2; mt++) {
                int rb = wm * 32 + mt * 16;
                uint32_t af[4];
                af[0] = As[ASW(rb + grp,     kk + tg)];
                af[1] = As[ASW(rb + grp + 8, kk + tg)];
                af[2] = As[ASW(rb + grp,     kk + tg + 4)];
                af[3] = As[ASW(rb + grp + 8, kk + tg + 4)];
#pragma unroll
                for (int nt = 0; nt < 8; nt++)
                    mma_tf32(acc[mt][nt], af, bf[nt]);
            }
        }
        __syncthreads();  // all reads of As done

        // write h1 = tf32(relu(acc + b1)) into As
#pragma unroll
        for (int mt = 0; mt < 2; mt++) {
            int r_lo = wm * 32 + mt * 16 + grp;
            int r_hi = r_lo + 8;
#pragma unroll
            for (int nt = 0; nt < 8; nt++) {
                int col = wn * 64 + nt * 8 + tg * 2;
                float b0 = s_b1[col], b1v = s_b1[col + 1];
                uint2 lo = { cvt_tf32(fmaxf(acc[mt][nt][0] + b0, 0.f)),
                             cvt_tf32(fmaxf(acc[mt][nt][1] + b1v, 0.f)) };
                uint2 hi = { cvt_tf32(fmaxf(acc[mt][nt][2] + b0, 0.f)),
                             cvt_tf32(fmaxf(acc[mt][nt][3] + b1v, 0.f)) };
                *(uint2*)(As + ASW(r_lo, col)) = lo;
                *(uint2*)(As + ASW(r_hi, col)) = hi;
            }
        }
        __syncthreads();

        // =========== layer 2: h1 @ w2 -> h2 ===========
#pragma unroll
        for (int mt = 0; mt < 2; mt++)
#pragma unroll
            for (int nt = 0; nt < 8; nt++)
#pragma unroll
                for (int i = 0; i < 4; i++) acc[mt][nt][i] = 0.f;

#pragma unroll
        for (int s = 0; s < 16; s++) {
            const int kk = s * 8;
            uint32_t bf[8][2];
#pragma unroll
            for (int nt = 0; nt < 8; nt++) {
                int n_sw = (wn * 64 + nt * 8 + grp) ^ (tg << 3);
                bf[nt][0] = W2s[((kk + tg) << 7) + n_sw];
                bf[nt][1] = W2s[((kk + tg + 4) << 7) + n_sw];
            }
#pragma unroll
            for (int mt = 0; mt < 2; mt++) {
                int rb = wm * 32 + mt * 16;
                uint32_t af[4];
                af[0] = As[ASW(rb + grp,     kk + tg)];
                af[1] = As[ASW(rb + grp + 8, kk + tg)];
                af[2] = As[ASW(rb + grp,     kk + tg + 4)];
                af[3] = As[ASW(rb + grp + 8, kk + tg + 4)];
#pragma unroll
                for (int nt = 0; nt < 8; nt++)
                    mma_tf32(acc[mt][nt], af, bf[nt]);
            }
        }
        __syncthreads();

        // write h2
#pragma unroll
        for (int mt = 0; mt < 2; mt++) {
            int r_lo = wm * 32 + mt * 16 + grp;
            int r_hi = r_lo + 8;
#pragma unroll
            for (int nt = 0; nt < 8; nt++) {
                int col = wn * 64 + nt * 8 + tg * 2;
                float b0 = s_b2[col], b1v = s_b2[col + 1];
                uint2 lo = { cvt_tf32(fmaxf(acc[mt][nt][0] + b0, 0.f)),
                             cvt_tf32(fmaxf(acc[mt][nt][1] + b1v, 0.f)) };
                uint2 hi = { cvt_tf32(fmaxf(acc[mt][nt][2] + b0, 0.f)),
                             cvt_tf32(fmaxf(acc[mt][nt][3] + b1v, 0.f)) };
                *(uint2*)(As + ASW(r_lo, col)) = lo;
                *(uint2*)(As + ASW(r_hi, col)) = hi;
            }
        }
        __syncthreads();

        // =========== layer 3: h2 @ w3 -> ee (fp32 out) ===========
#pragma unroll
        for (int mt = 0; mt < 2; mt++)
#pragma unroll
            for (int nt = 0; nt < 8; nt++)
#pragma unroll
                for (int i = 0; i < 4; i++) acc[mt][nt][i] = 0.f;

#pragma unroll
        for (int s = 0; s < 16; s++) {
            const int kk = s * 8;
            uint32_t bf[8][2];
#pragma unroll
            for (int nt = 0; nt < 8; nt++) {
                int n_sw = (wn * 64 + nt * 8 + grp) ^ (tg << 3);
                bf[nt][0] = W3s[((kk + tg) << 7) + n_sw];
                bf[nt][1] = W3s[((kk + tg + 4) << 7) + n_sw];
            }
#pragma unroll
            for (int mt = 0; mt < 2; mt++) {
                int rb = wm * 32 + mt * 16;
                uint32_t af[4];
                af[0] = As[ASW(rb + grp,     kk + tg)];
                af[1] = As[ASW(rb + grp + 8, kk + tg)];
                af[2] = As[ASW(rb + grp,     kk + tg + 4)];
                af[3] = As[ASW(rb + grp + 8, kk + tg + 4)];
#pragma unroll
                for (int nt = 0; nt < 8; nt++)
                    mma_tf32(acc[mt][nt], af, bf[nt]);
            }
        }
        __syncthreads();  // As free for next tile's gather

        // epilogue: ee = relu(acc + b3), fp32 to gmem
#pragma unroll
        for (int mt = 0; mt < 2; mt++) {
            int r_lo = wm * 32 + mt * 16 + grp;
            int r_hi = r_lo + 8;
            bool v_lo = (e0 + r_lo) < e_cnt;
            bool v_hi = (e0 + r_hi) < e_cnt;
#pragma unroll
            for (int nt = 0; nt < 8; nt++) {
                int col = wn * 64 + nt * 8 + tg * 2;
                float b0 = s_b3[col], b1v = s_b3[col + 1];
                if (v_lo) {
                    float2 v = { fmaxf(acc[mt][nt][0] + b0, 0.f),
                                 fmaxf(acc[mt][nt][1] + b1v, 0.f) };
                    *(float2*)(ee + (size_t)(e0 + r_lo) * NF + col) = v;
                }
                if (v_hi) {
                    float2 v = { fmaxf(acc[mt][nt][2] + b0, 0.f),
                                 fmaxf(acc[mt][nt][3] + b1v, 0.f) };
                    *(float2*)(ee + (size_t)(e0 + r_hi) * NF + col) = v;
                }
            }
        }
        // next tile's idx staging conflicts only with gather (synced above)
    }
}

// ---------------------------------------------------------------------------
// Relation propagator via mma.sync tf32 + fused segment_sum. (round-3, passing)
// ---------------------------------------------------------------------------
#define A_STRIDE 36
#define B_STRIDE 136
#define OFF_RECV 0
#define OFF_SEND 512
#define OFF_BIAS 1024
#define OFF_A    1536
#define OFF_B    (OFF_A + 128 * A_STRIDE * 4)
#define RP_SMEM_BYTES (OFF_B + 384 * B_STRIDE * 4)

__global__ __launch_bounds__(256, 1) void k_rel_prop_mma(
    const float* __restrict__ ee, const float* __restrict__ eff,
    const int* __restrict__ recv, const int* __restrict__ send,
    const float* __restrict__ w, const float* __restrict__ b,
    float* __restrict__ agg, int e_cnt)
{
    extern __shared__ char smem[];
    int*      s_recv = (int*)     (smem + OFF_RECV);
    int*      s_send = (int*)     (smem + OFF_SEND);
    float*    s_bias = (float*)   (smem + OFF_BIAS);
    uint32_t* As     = (uint32_t*)(smem + OFF_A);
    uint32_t* Bs     = (uint32_t*)(smem + OFF_B);

    const int tid = threadIdx.x;
    const int wid = tid >> 5;
    const int lane = tid & 31;
    const int grp = lane >> 2;
    const int tg  = lane & 3;
    const int wm  = wid & 3;
    const int wn  = wid >> 2;

    for (int idx = tid; idx < 384 * 128; idx += 256) {
        int k = idx >> 7, n = idx & 127;
        Bs[k * B_STRIDE + n] = cvt_tf32(w[k * NF + n]);
    }
    if (tid < 128) s_bias[tid] = b[tid];
    __syncthreads();

    const int ntiles = (e_cnt + 127) >> 7;
    const int r_st   = tid >> 1;
    const int half   = tid & 1;

    for (int tile = blockIdx.x; tile < ntiles; tile += gridDim.x) {
        const int e0 = tile << 7;
        if (tid < 128) {
            int e = e0 + tid;
            s_recv[tid] = (e < e_cnt) ? recv[e] : 0;
            s_send[tid] = (e < e_cnt) ? send[e] : 0;
        }

        float acc[2][8][4];
#pragma unroll
        for (int mt = 0; mt < 2; mt++)
#pragma unroll
            for (int nt = 0; nt < 8; nt++)
#pragma unroll
                for (int i = 0; i < 4; i++) acc[mt][nt][i] = 0.f;

        __syncthreads();

        for (int c = 0; c < 12; c++) {
            const float* src;
            bool valid = true;
            if (c < 4) {
                int e = e0 + r_st;
                valid = (e < e_cnt);
                src = ee + (size_t)e * NF + c * 32;
            } else if (c < 8) {
                src = eff + (size_t)s_recv[r_st] * NF + (c - 4) * 32;
            } else {
                src = eff + (size_t)s_send[r_st] * NF + (c - 8) * 32;
            }
            uint32_t* dst = As + r_st * A_STRIDE + half * 16;
#pragma unroll
            for (int q = 0; q < 4; q++) {
                float4 v = valid ? *(const float4*)(src + half * 16 + q * 4)
                                 : make_float4(0.f, 0.f, 0.f, 0.f);
                uint4 u;
                u.x = cvt_tf32(v.x); u.y = cvt_tf32(v.y);
                u.z = cvt_tf32(v.z); u.w = cvt_tf32(v.w);
                *(uint4*)(dst + q * 4) = u;
            }
            __syncthreads();

#pragma unroll
            for (int s = 0; s < 4; s++) {
                const int kk = c * 32 + s * 8;
                const int ac = s * 8;

                uint32_t bf[8][2];
#pragma unroll
                for (int nt = 0; nt < 8; nt++) {
                    int n = wn * 64 + nt * 8 + grp;
                    bf[nt][0] = Bs[(kk + tg)     * B_STRIDE + n];
                    bf[nt][1] = Bs[(kk + tg + 4) * B_STRIDE + n];
                }
#pragma unroll
                for (int mt = 0; mt < 2; mt++) {
                    int rb = wm * 32 + mt * 16;
                    uint32_t af[4];
                    af[0] = As[(rb + grp)     * A_STRIDE + ac + tg];
                    af[1] = As[(rb + grp + 8) * A_STRIDE + ac + tg];
                    af[2] = As[(rb + grp)     * A_STRIDE + ac + tg + 4];
                    af[3] = As[(rb + grp + 8) * A_STRIDE + ac + tg + 4];
#pragma unroll
                    for (int nt = 0; nt < 8; nt++)
                        mma_tf32(acc[mt][nt], af, bf[nt]);
                }
            }
            __syncthreads();
        }

#pragma unroll
        for (int mt = 0; mt < 2; mt++) {
            int r_lo = wm * 32 + mt * 16 + grp;
            int r_hi = r_lo + 8;
            bool v_lo = (e0 + r_lo) < e_cnt;
            bool v_hi = (e0 + r_hi) < e_cnt;
            int d_lo = s_recv[r_lo];
            int d_hi = s_recv[r_hi];
#pragma unroll
            for (int nt = 0; nt < 8; nt++) {
                int col = wn * 64 + nt * 8 + tg * 2;
                float b0 = s_bias[col], b1 = s_bias[col + 1];
                if (v_lo) {
                    atomicAdd(&agg[(size_t)d_lo * NF + col],     fmaxf(acc[mt][nt][0] + b0, 0.f));
                    atomicAdd(&agg[(size_t)d_lo * NF + col + 1], fmaxf(acc[mt][nt][1] + b1, 0.f));
                }
                if (v_hi) {
                    atomicAdd(&agg[(size_t)d_hi * NF + col],     fmaxf(acc[mt][nt][2] + b0, 0.f));
                    atomicAdd(&agg[(size_t)d_hi * NF + col + 1], fmaxf(acc[mt][nt][3] + b1, 0.f));
                }
            }
        }
        __syncthreads();
    }
}

// ---------------------------------------------------------------------------
// Particle propagator: eff = relu([pe, agg] @ pp_w + pp_b)
// ---------------------------------------------------------------------------
__global__ __launch_bounds__(128) void k_part_prop(
    const float* __restrict__ pe, const float* __restrict__ agg,
    const float* __restrict__ w, const float* __restrict__ b,
    float* __restrict__ eff, int n)
{
    const int RB = 8;
    const int KIN = 2 * NF; // 256
    __shared__ float s_in[RB][KIN];

    int row0 = blockIdx.x * RB;
    int t = threadIdx.x;

#pragma unroll
    for (int r = 0; r < RB; r++) {
        int row = row0 + r;
        s_in[r][t]      = (row < n) ? pe [row * NF + t] : 0.f;
        s_in[r][NF + t] = (row < n) ? agg[row * NF + t] : 0.f;
    }
    __syncthreads();

    float acc[RB];
#pragma unroll
    for (int r = 0; r < RB; r++) acc[r] = b[t];
#pragma unroll 4
    for (int k = 0; k < KIN; k++) {
        float wv = w[k * NF + t];
#pragma unroll
        for (int r = 0; r < RB; r++) acc[r] = fmaf(s_in[r][k], wv, acc[r]);
    }
#pragma unroll
    for (int r = 0; r < RB; r++) {
        int row = row0 + r;
        if (row < n) eff[row * NF + t] = fmaxf(acc[r], 0.f);
    }
}

// ---------------------------------------------------------------------------
// Decoder: out = relu(relu(eff@w1+b1)@w2+b2) @ w3 + b3  ([N,3])
// ---------------------------------------------------------------------------
__global__ __launch_bounds__(128) void k_decoder(
    const float* __restrict__ eff,
    const float* __restrict__ w1, const float* __restrict__ b1,
    const float* __restrict__ w2, const float* __restrict__ b2,
    const float* __restrict__ w3, const float* __restrict__ b3,
    float* __restrict__ out, int n)
{
    const int RB = 8;
    __shared__ float s_in[RB][NF];
    __shared__ float s_h1[RB][NF];
    __shared__ float s_h2[RB][NF];

    int row0 = blockIdx.x * RB;
    int t = threadIdx.x;

#pragma unroll
    for (int r = 0; r < RB; r++) {
        int row = row0 + r;
        s_in[r][t] = (row < n) ? eff[row * NF + t] : 0.f;
    }
    __syncthreads();

    float acc[RB];
#pragma unroll
    for (int r = 0; r < RB; r++) acc[r] = b1[t];
#pragma unroll 4
    for (int k = 0; k < NF; k++) {
        float w = w1[k * NF + t];
#pragma unroll
        for (int r = 0; r < RB; r++) acc[r] = fmaf(s_in[r][k], w, acc[r]);
    }
#pragma unroll
    for (int r = 0; r < RB; r++) s_h1[r][t] = fmaxf(acc[r], 0.f);
    __syncthreads();

#pragma unroll
    for (int r = 0; r < RB; r++) acc[r] = b2[t];
#pragma unroll 4
    for (int k = 0; k < NF; k++) {
        float w = w2[k * NF + t];
#pragma unroll
        for (int r = 0; r < RB; r++) acc[r] = fmaf(s_h1[r][k], w, acc[r]);
    }
#pragma unroll
    for (int r = 0; r < RB; r++) s_h2[r][t] = fmaxf(acc[r], 0.f);
    __syncthreads();

    if (t < RB * 3) {
        int r = t / 3, j = t % 3;
        int row = row0 + r;
        if (row < n) {
            float a = b3[j];
#pragma unroll 4
            for (int k = 0; k < NF; k++)
                a = fmaf(s_h2[r][k], w3[k * 3 + j], a);
            out[row * 3 + j] = a;
        }
    }
}

// ---------------------------------------------------------------------------
// launch
// ---------------------------------------------------------------------------
extern "C" void kernel_launch(void* const* d_in, const int* in_sizes, int n_in,
                              void* d_out, int out_size)
{
    const float* attr  = (const float*)d_in[0];
    const float* state = (const float*)d_in[1];
    const float* Ra    = (const float*)d_in[2];
    const int*   recv  = (const int*)  d_in[3];
    const int*   send  = (const int*)  d_in[4];
    // d_in[5] = pstep (device scalar; fixed to 2 for this problem)
    const float* pe_w1 = (const float*)d_in[6];
    const float* pe_b1 = (const float*)d_in[7];
    const float* pe_w2 = (const float*)d_in[8];
    const float* pe_b2 = (const float*)d_in[9];
    const float* ee_w1 = (const float*)d_in[10];
    const float* ee_b1 = (const float*)d_in[11];
    const float* ee_w2 = (const float*)d_in[12];
    const float* ee_b2 = (const float*)d_in[13];
    const float* ee_w3 = (const float*)d_in[14];
    const float* ee_b3 = (const float*)d_in[15];
    const float* rp_w  = (const float*)d_in[16];
    const float* rp_b  = (const float*)d_in[17];
    const float* pp_w  = (const float*)d_in[18];
    const float* pp_b  = (const float*)d_in[19];
    const float* de_w1 = (const float*)d_in[20];
    const float* de_b1 = (const float*)d_in[21];
    const float* de_w2 = (const float*)d_in[22];
    const float* de_b2 = (const float*)d_in[23];
    const float* de_w3 = (const float*)d_in[24];
    const float* de_b3 = (const float*)d_in[25];

    const int n = in_sizes[0] / ATTR_W;   // 100000
    const int e = in_sizes[2] / REL_W;    // 500000

    float *pe, *ee, *eff, *agg;
    cudaGetSymbolAddress((void**)&pe,  g_pe);
    cudaGetSymbolAddress((void**)&ee,  g_ee);
    cudaGetSymbolAddress((void**)&eff, g_eff);
    cudaGetSymbolAddress((void**)&agg, g_agg);

    cudaFuncSetAttribute(k_rel_prop_mma,
                         cudaFuncAttributeMaxDynamicSharedMemorySize, RP_SMEM_BYTES);
    cudaFuncSetAttribute(k_edge_enc_mma,
                         cudaFuncAttributeMaxDynamicSharedMemorySize, EE_SMEM_BYTES);

    const int RB_N = 8;
    dim3 blk(128);

    // effect starts at zero
    k_zero<<<1024, 256>>>(eff, n * NF);

    // encoders
    k_node_enc<<<(n + RB_N - 1) / RB_N, blk>>>(attr, state, pe_w1, pe_b1, pe_w2, pe_b2, pe, n);
    k_edge_enc_mma<<<148, 256, EE_SMEM_BYTES>>>(attr, state, Ra, recv, send,
                                                ee_w1, ee_b1, ee_w2, ee_b2, ee_w3, ee_b3, ee, e);

    // propagation (pstep = 2)
    for (int ps = 0; ps < PSTEP; ps++) {
        k_zero<<<1024, 256>>>(agg, n * NF);
        k_rel_prop_mma<<<148, 256, RP_SMEM_BYTES>>>(ee, eff, recv, send, rp_w, rp_b, agg, e);
        k_part_prop<<<(n + RB_N - 1) / RB_N, blk>>>(pe, agg, pp_w, pp_b, eff, n);
    }

    // decoder
    k_decoder<<<(n + RB_N - 1) / RB_N, blk>>>(eff, de_w1, de_b1, de_w2, de_b2, de_w3, de_b3,
                                              (float*)d_out, n);
}

// round 5
// speedup vs baseline: 3.5169x; 1.4946x over previous
#include <cuda_runtime.h>
#include <cuda_bf16.h>
#include <cstdint>

// Problem constants (fixed by the dataset)
#define NN 100000
#define EE 500000
#define NF 128
#define ATTR_W 16
#define STATE_W 12
#define REL_W 4
#define PSTEP 2

// Scratch (device globals; no runtime allocation allowed)
__device__ float g_pe [NN * NF];
__device__ float g_ee [EE * NF];
__device__ float g_eff[NN * NF];
__device__ float g_agg[NN * NF];

// ---------------------------------------------------------------------------
// helpers
// ---------------------------------------------------------------------------
__device__ __forceinline__ uint32_t cvt_tf32(float x) {
    uint32_t r;
    asm("cvt.rna.tf32.f32 %0, %1;" : "=r"(r) : "f"(x));
    return r;
}

__device__ __forceinline__ void mma_tf32(float* c, const uint32_t* a, const uint32_t* b) {
    asm volatile(
        "mma.sync.aligned.m16n8k8.row.col.f32.tf32.tf32.f32 "
        "{%0,%1,%2,%3}, {%4,%5,%6,%7}, {%8,%9}, {%0,%1,%2,%3};"
        : "+f"(c[0]), "+f"(c[1]), "+f"(c[2]), "+f"(c[3])
        : "r"(a[0]), "r"(a[1]), "r"(a[2]), "r"(a[3]), "r"(b[0]), "r"(b[1]));
}

// vector reduction to gmem (sm_90+): 2 floats per op
__device__ __forceinline__ void red2(float* p, float a, float b) {
    asm volatile("red.global.add.v2.f32 [%0], {%1, %2};" :: "l"(p), "f"(a), "f"(b) : "memory");
}

// weight swizzle: [K x 128], addr = k*128 + (n ^ ((k&3)<<3))
#define WSW(k, n) (((k) << 7) + ((n) ^ (((k) & 3) << 3)))
// activation swizzle (stride 128): addr = r*128 + (c ^ ((r&7)<<2))
#define ASW(r, c) (((r) << 7) + ((c) ^ (((r) & 7) << 2)))
// chunk swizzle (stride 32): addr = r*32 + (c ^ ((r&7)<<2)), c in 0..31
#define ACSW(r, c) (((r) << 5) + ((c) ^ (((r) & 7) << 2)))

// ---------------------------------------------------------------------------
// zero kernel
// ---------------------------------------------------------------------------
__global__ void k_zero(float* p, int n) {
    int i = blockIdx.x * blockDim.x + threadIdx.x;
    int stride = gridDim.x * blockDim.x;
    for (; i < n; i += stride) p[i] = 0.0f;
}

// ---------------------------------------------------------------------------
// Node encoder (scalar; small)
// ---------------------------------------------------------------------------
__global__ __launch_bounds__(128) void k_node_enc(
    const float* __restrict__ attr, const float* __restrict__ state,
    const float* __restrict__ w1, const float* __restrict__ b1,
    const float* __restrict__ w2, const float* __restrict__ b2,
    float* __restrict__ pe, int n)
{
    const int RB = 8;
    const int KIN = ATTR_W + STATE_W; // 28
    __shared__ float s_in[RB][KIN];
    __shared__ float s_h1[RB][NF];

    int row0 = blockIdx.x * RB;
    int t = threadIdx.x;

    for (int i = t; i < RB * KIN; i += 128) {
        int r = i / KIN, f = i % KIN;
        int row = row0 + r;
        float v = 0.f;
        if (row < n)
            v = (f < ATTR_W) ? attr[row * ATTR_W + f]
                             : state[row * STATE_W + (f - ATTR_W)];
        s_in[r][f] = v;
    }
    __syncthreads();

    float acc[RB];
#pragma unroll
    for (int r = 0; r < RB; r++) acc[r] = b1[t];
#pragma unroll 4
    for (int k = 0; k < KIN; k++) {
        float w = w1[k * NF + t];
#pragma unroll
        for (int r = 0; r < RB; r++) acc[r] = fmaf(s_in[r][k], w, acc[r]);
    }
#pragma unroll
    for (int r = 0; r < RB; r++) s_h1[r][t] = fmaxf(acc[r], 0.f);
    __syncthreads();

#pragma unroll
    for (int r = 0; r < RB; r++) acc[r] = b2[t];
#pragma unroll 4
    for (int k = 0; k < NF; k++) {
        float w = w2[k * NF + t];
#pragma unroll
        for (int r = 0; r < RB; r++) acc[r] = fmaf(s_h1[r][k], w, acc[r]);
    }
#pragma unroll
    for (int r = 0; r < RB; r++) {
        int row = row0 + r;
        if (row < n) pe[row * NF + t] = fmaxf(acc[r], 0.f);
    }
}

// ---------------------------------------------------------------------------
// Edge encoder via mma.sync tf32 (round-4, passing)
// ---------------------------------------------------------------------------
#define EE_OFF_RECV 0
#define EE_OFF_SEND 512
#define EE_OFF_B1   1024
#define EE_OFF_B2   1536
#define EE_OFF_B3   2048
#define EE_OFF_W1   2560
#define EE_OFF_W2   (EE_OFF_W1 + 32768)
#define EE_OFF_W3   (EE_OFF_W2 + 65536)
#define EE_OFF_ACT  (EE_OFF_W3 + 65536)
#define EE_SMEM_BYTES (EE_OFF_ACT + 65536)

__global__ __launch_bounds__(256, 1) void k_edge_enc_mma(
    const float* __restrict__ attr, const float* __restrict__ state,
    const float* __restrict__ Ra,
    const int* __restrict__ recv, const int* __restrict__ send,
    const float* __restrict__ w1, const float* __restrict__ b1,
    const float* __restrict__ w2, const float* __restrict__ b2,
    const float* __restrict__ w3, const float* __restrict__ b3,
    float* __restrict__ ee, int e_cnt)
{
    extern __shared__ char smem[];
    int*      s_recv = (int*)     (smem + EE_OFF_RECV);
    int*      s_send = (int*)     (smem + EE_OFF_SEND);
    float*    s_b1   = (float*)   (smem + EE_OFF_B1);
    float*    s_b2   = (float*)   (smem + EE_OFF_B2);
    float*    s_b3   = (float*)   (smem + EE_OFF_B3);
    uint32_t* W1s    = (uint32_t*)(smem + EE_OFF_W1);
    uint32_t* W2s    = (uint32_t*)(smem + EE_OFF_W2);
    uint32_t* W3s    = (uint32_t*)(smem + EE_OFF_W3);
    uint32_t* As     = (uint32_t*)(smem + EE_OFF_ACT);

    const int tid = threadIdx.x;
    const int wid = tid >> 5;
    const int lane = tid & 31;
    const int grp = lane >> 2;
    const int tg  = lane & 3;
    const int wm  = wid & 3;
    const int wn  = wid >> 2;

    for (int idx = tid; idx < 64 * 128; idx += 256) {
        int k = idx >> 7, n = idx & 127;
        float v = (k < 60) ? w1[k * NF + n] : 0.f;
        W1s[WSW(k, n)] = cvt_tf32(v);
    }
    for (int idx = tid; idx < 128 * 128; idx += 256) {
        int k = idx >> 7, n = idx & 127;
        W2s[WSW(k, n)] = cvt_tf32(w2[k * NF + n]);
        W3s[WSW(k, n)] = cvt_tf32(w3[k * NF + n]);
    }
    if (tid < 128) { s_b1[tid] = b1[tid]; s_b2[tid] = b2[tid]; s_b3[tid] = b3[tid]; }

    const int ntiles = (e_cnt + 127) >> 7;
    const int r_st   = tid >> 1;
    const int half   = tid & 1;

    float acc[2][8][4];

    __syncthreads();

    for (int tile = blockIdx.x; tile < ntiles; tile += gridDim.x) {
        const int e0 = tile << 7;
        if (tid < 128) {
            int e = e0 + tid;
            s_recv[tid] = (e < e_cnt) ? recv[e] : 0;
            s_send[tid] = (e < e_cnt) ? send[e] : 0;
        }
        __syncthreads();

        {
            int rv = s_recv[r_st], sv = s_send[r_st];
            int e  = e0 + r_st;
            if (half == 0) {
#pragma unroll
                for (int q = 0; q < 4; q++) {
                    float4 v = *(const float4*)(attr + (size_t)rv * ATTR_W + q * 4);
                    uint4 u = { cvt_tf32(v.x), cvt_tf32(v.y), cvt_tf32(v.z), cvt_tf32(v.w) };
                    *(uint4*)(As + ASW(r_st, q * 4)) = u;
                }
#pragma unroll
                for (int q = 0; q < 4; q++) {
                    float4 v = *(const float4*)(attr + (size_t)sv * ATTR_W + q * 4);
                    uint4 u = { cvt_tf32(v.x), cvt_tf32(v.y), cvt_tf32(v.z), cvt_tf32(v.w) };
                    *(uint4*)(As + ASW(r_st, 16 + q * 4)) = u;
                }
            } else {
#pragma unroll
                for (int q = 0; q < 3; q++) {
                    float4 v = *(const float4*)(state + (size_t)rv * STATE_W + q * 4);
                    uint4 u = { cvt_tf32(v.x), cvt_tf32(v.y), cvt_tf32(v.z), cvt_tf32(v.w) };
                    *(uint4*)(As + ASW(r_st, 32 + q * 4)) = u;
                }
#pragma unroll
                for (int q = 0; q < 3; q++) {
                    float4 v = *(const float4*)(state + (size_t)sv * STATE_W + q * 4);
                    uint4 u = { cvt_tf32(v.x), cvt_tf32(v.y), cvt_tf32(v.z), cvt_tf32(v.w) };
                    *(uint4*)(As + ASW(r_st, 44 + q * 4)) = u;
                }
                {
                    float4 v = (e < e_cnt) ? *(const float4*)(Ra + (size_t)e * REL_W)
                                           : make_float4(0.f, 0.f, 0.f, 0.f);
                    uint4 u = { cvt_tf32(v.x), cvt_tf32(v.y), cvt_tf32(v.z), cvt_tf32(v.w) };
                    *(uint4*)(As + ASW(r_st, 56)) = u;
                }
                {
                    uint4 u = { 0u, 0u, 0u, 0u };
                    *(uint4*)(As + ASW(r_st, 60)) = u;
                }
            }
        }
        __syncthreads();

        // layer 1 (k=64)
#pragma unroll
        for (int mt = 0; mt < 2; mt++)
#pragma unroll
            for (int nt = 0; nt < 8; nt++)
#pragma unroll
                for (int i = 0; i < 4; i++) acc[mt][nt][i] = 0.f;
#pragma unroll
        for (int s = 0; s < 8; s++) {
            const int kk = s * 8;
            uint32_t bf[8][2];
#pragma unroll
            for (int nt = 0; nt < 8; nt++) {
                int n_sw = (wn * 64 + nt * 8 + grp) ^ (tg << 3);
                bf[nt][0] = W1s[((kk + tg) << 7) + n_sw];
                bf[nt][1] = W1s[((kk + tg + 4) << 7) + n_sw];
            }
#pragma unroll
            for (int mt = 0; mt < 2; mt++) {
                int rb = wm * 32 + mt * 16;
                uint32_t af[4];
                af[0] = As[ASW(rb + grp,     kk + tg)];
                af[1] = As[ASW(rb + grp + 8, kk + tg)];
                af[2] = As[ASW(rb + grp,     kk + tg + 4)];
                af[3] = As[ASW(rb + grp + 8, kk + tg + 4)];
#pragma unroll
                for (int nt = 0; nt < 8; nt++)
                    mma_tf32(acc[mt][nt], af, bf[nt]);
            }
        }
        __syncthreads();

#pragma unroll
        for (int mt = 0; mt < 2; mt++) {
            int r_lo = wm * 32 + mt * 16 + grp;
            int r_hi = r_lo + 8;
#pragma unroll
            for (int nt = 0; nt < 8; nt++) {
                int col = wn * 64 + nt * 8 + tg * 2;
                float b0 = s_b1[col], b1v = s_b1[col + 1];
                uint2 lo = { cvt_tf32(fmaxf(acc[mt][nt][0] + b0, 0.f)),
                             cvt_tf32(fmaxf(acc[mt][nt][1] + b1v, 0.f)) };
                uint2 hi = { cvt_tf32(fmaxf(acc[mt][nt][2] + b0, 0.f)),
                             cvt_tf32(fmaxf(acc[mt][nt][3] + b1v, 0.f)) };
                *(uint2*)(As + ASW(r_lo, col)) = lo;
                *(uint2*)(As + ASW(r_hi, col)) = hi;
            }
        }
        __syncthreads();

        // layer 2 (k=128)
#pragma unroll
        for (int mt = 0; mt < 2; mt++)
#pragma unroll
            for (int nt = 0; nt < 8; nt++)
#pragma unroll
                for (int i = 0; i < 4; i++) acc[mt][nt][i] = 0.f;
#pragma unroll
        for (int s = 0; s < 16; s++) {
            const int kk = s * 8;
            uint32_t bf[8][2];
#pragma unroll
            for (int nt = 0; nt < 8; nt++) {
                int n_sw = (wn * 64 + nt * 8 + grp) ^ (tg << 3);
                bf[nt][0] = W2s[((kk + tg) << 7) + n_sw];
                bf[nt][1] = W2s[((kk + tg + 4) << 7) + n_sw];
            }
#pragma unroll
            for (int mt = 0; mt < 2; mt++) {
                int rb = wm * 32 + mt * 16;
                uint32_t af[4];
                af[0] = As[ASW(rb + grp,     kk + tg)];
                af[1] = As[ASW(rb + grp + 8, kk + tg)];
                af[2] = As[ASW(rb + grp,     kk + tg + 4)];
                af[3] = As[ASW(rb + grp + 8, kk + tg + 4)];
#pragma unroll
                for (int nt = 0; nt < 8; nt++)
                    mma_tf32(acc[mt][nt], af, bf[nt]);
            }
        }
        __syncthreads();

#pragma unroll
        for (int mt = 0; mt < 2; mt++) {
            int r_lo = wm * 32 + mt * 16 + grp;
            int r_hi = r_lo + 8;
#pragma unroll
            for (int nt = 0; nt < 8; nt++) {
                int col = wn * 64 + nt * 8 + tg * 2;
                float b0 = s_b2[col], b1v = s_b2[col + 1];
                uint2 lo = { cvt_tf32(fmaxf(acc[mt][nt][0] + b0, 0.f)),
                             cvt_tf32(fmaxf(acc[mt][nt][1] + b1v, 0.f)) };
                uint2 hi = { cvt_tf32(fmaxf(acc[mt][nt][2] + b0, 0.f)),
                             cvt_tf32(fmaxf(acc[mt][nt][3] + b1v, 0.f)) };
                *(uint2*)(As + ASW(r_lo, col)) = lo;
                *(uint2*)(As + ASW(r_hi, col)) = hi;
            }
        }
        __syncthreads();

        // layer 3 (k=128) -> ee
#pragma unroll
        for (int mt = 0; mt < 2; mt++)
#pragma unroll
            for (int nt = 0; nt < 8; nt++)
#pragma unroll
                for (int i = 0; i < 4; i++) acc[mt][nt][i] = 0.f;
#pragma unroll
        for (int s = 0; s < 16; s++) {
            const int kk = s * 8;
            uint32_t bf[8][2];
#pragma unroll
            for (int nt = 0; nt < 8; nt++) {
                int n_sw = (wn * 64 + nt * 8 + grp) ^ (tg << 3);
                bf[nt][0] = W3s[((kk + tg) << 7) + n_sw];
                bf[nt][1] = W3s[((kk + tg + 4) << 7) + n_sw];
            }
#pragma unroll
            for (int mt = 0; mt < 2; mt++) {
                int rb = wm * 32 + mt * 16;
                uint32_t af[4];
                af[0] = As[ASW(rb + grp,     kk + tg)];
                af[1] = As[ASW(rb + grp + 8, kk + tg)];
                af[2] = As[ASW(rb + grp,     kk + tg + 4)];
                af[3] = As[ASW(rb + grp + 8, kk + tg + 4)];
#pragma unroll
                for (int nt = 0; nt < 8; nt++)
                    mma_tf32(acc[mt][nt], af, bf[nt]);
            }
        }
        __syncthreads();

#pragma unroll
        for (int mt = 0; mt < 2; mt++) {
            int r_lo = wm * 32 + mt * 16 + grp;
            int r_hi = r_lo + 8;
            bool v_lo = (e0 + r_lo) < e_cnt;
            bool v_hi = (e0 + r_hi) < e_cnt;
#pragma unroll
            for (int nt = 0; nt < 8; nt++) {
                int col = wn * 64 + nt * 8 + tg * 2;
                float b0 = s_b3[col], b1v = s_b3[col + 1];
                if (v_lo) {
                    float2 v = { fmaxf(acc[mt][nt][0] + b0, 0.f),
                                 fmaxf(acc[mt][nt][1] + b1v, 0.f) };
                    *(float2*)(ee + (size_t)(e0 + r_lo) * NF + col) = v;
                }
                if (v_hi) {
                    float2 v = { fmaxf(acc[mt][nt][2] + b0, 0.f),
                                 fmaxf(acc[mt][nt][3] + b1v, 0.f) };
                    *(float2*)(ee + (size_t)(e0 + r_hi) * NF + col) = v;
                }
            }
        }
    }
}

// ---------------------------------------------------------------------------
// Relation propagator v2: double-buffered chunks + XOR swizzle + red.v2
// ---------------------------------------------------------------------------
#define RP2_OFF_RECV 0
#define RP2_OFF_SEND 512
#define RP2_OFF_BIAS 1024
#define RP2_OFF_A0   1536
#define RP2_OFF_A1   (RP2_OFF_A0 + 16384)
#define RP2_OFF_B    (RP2_OFF_A1 + 16384)             // 34304
#define RP2_SMEM_BYTES (RP2_OFF_B + 384 * 128 * 4)    // 230912

__global__ __launch_bounds__(256, 1) void k_rel_prop_mma(
    const float* __restrict__ ee, const float* __restrict__ eff,
    const int* __restrict__ recv, const int* __restrict__ send,
    const float* __restrict__ w, const float* __restrict__ b,
    float* __restrict__ agg, int e_cnt)
{
    extern __shared__ char smem[];
    int*      s_recv = (int*)     (smem + RP2_OFF_RECV);
    int*      s_send = (int*)     (smem + RP2_OFF_SEND);
    float*    s_bias = (float*)   (smem + RP2_OFF_BIAS);
    uint32_t* A0     = (uint32_t*)(smem + RP2_OFF_A0);
    uint32_t* A1     = (uint32_t*)(smem + RP2_OFF_A1);
    uint32_t* Bs     = (uint32_t*)(smem + RP2_OFF_B);

    const int tid = threadIdx.x;
    const int wid = tid >> 5;
    const int lane = tid & 31;
    const int grp = lane >> 2;
    const int tg  = lane & 3;
    const int wm  = wid & 3;
    const int wn  = wid >> 2;

    for (int idx = tid; idx < 384 * 128; idx += 256) {
        int k = idx >> 7, n = idx & 127;
        Bs[WSW(k, n)] = cvt_tf32(w[k * NF + n]);
    }
    if (tid < 128) s_bias[tid] = b[tid];
    __syncthreads();

    const int ntiles = (e_cnt + 127) >> 7;
    const int r_st   = tid >> 1;
    const int half   = tid & 1;

    for (int tile = blockIdx.x; tile < ntiles; tile += gridDim.x) {
        const int e0 = tile << 7;
        if (tid < 128) {
            int e = e0 + tid;
            s_recv[tid] = (e < e_cnt) ? recv[e] : 0;
            s_send[tid] = (e < e_cnt) ? send[e] : 0;
        }

        float acc[2][8][4];
#pragma unroll
        for (int mt = 0; mt < 2; mt++)
#pragma unroll
            for (int nt = 0; nt < 8; nt++)
#pragma unroll
                for (int i = 0; i < 4; i++) acc[mt][nt][i] = 0.f;

        __syncthreads();   // idx visible; prev-tile epilogue reads done

        // prefetch chunk 0 (ee rows; contiguous)
        float4 pv[4];
        {
            int e = e0 + r_st;
            bool valid = (e < e_cnt);
            const float* src = ee + (size_t)e * NF;   // chunk 0 cols 0..31
#pragma unroll
            for (int q = 0; q < 4; q++)
                pv[q] = valid ? *(const float4*)(src + half * 16 + q * 4)
                              : make_float4(0.f, 0.f, 0.f, 0.f);
        }

        for (int c = 0; c < 12; c++) {
            uint32_t* Abuf = (c & 1) ? A1 : A0;
            // store prefetched regs -> Abuf (tf32, swizzled)
#pragma unroll
            for (int q = 0; q < 4; q++) {
                uint4 u = { cvt_tf32(pv[q].x), cvt_tf32(pv[q].y),
                            cvt_tf32(pv[q].z), cvt_tf32(pv[q].w) };
                *(uint4*)(Abuf + ACSW(r_st, half * 16 + q * 4)) = u;
            }
            __syncthreads();

            // prefetch next chunk
            if (c < 11) {
                int cn = c + 1;
                const float* src;
                bool valid = true;
                if (cn < 4) {
                    int e = e0 + r_st;
                    valid = (e < e_cnt);
                    src = ee + (size_t)e * NF + cn * 32;
                } else if (cn < 8) {
                    src = eff + (size_t)s_recv[r_st] * NF + (cn - 4) * 32;
                } else {
                    src = eff + (size_t)s_send[r_st] * NF + (cn - 8) * 32;
                }
#pragma unroll
                for (int q = 0; q < 4; q++)
                    pv[q] = valid ? *(const float4*)(src + half * 16 + q * 4)
                                  : make_float4(0.f, 0.f, 0.f, 0.f);
            }

            // MMAs on Abuf
            const int kb = c * 32;
#pragma unroll
            for (int s = 0; s < 4; s++) {
                const int ac = s * 8;
                const int kk = kb + ac;
                uint32_t bf[8][2];
#pragma unroll
                for (int nt = 0; nt < 8; nt++) {
                    int n_sw = (wn * 64 + nt * 8 + grp) ^ (tg << 3);
                    bf[nt][0] = Bs[((kk + tg) << 7) + n_sw];
                    bf[nt][1] = Bs[((kk + tg + 4) << 7) + n_sw];
                }
#pragma unroll
                for (int mt = 0; mt < 2; mt++) {
                    int rb = wm * 32 + mt * 16;
                    uint32_t af[4];
                    af[0] = Abuf[ACSW(rb + grp,     ac + tg)];
                    af[1] = Abuf[ACSW(rb + grp + 8, ac + tg)];
                    af[2] = Abuf[ACSW(rb + grp,     ac + tg + 4)];
                    af[3] = Abuf[ACSW(rb + grp + 8, ac + tg + 4)];
#pragma unroll
                    for (int nt = 0; nt < 8; nt++)
                        mma_tf32(acc[mt][nt], af, bf[nt]);
                }
            }
        }

        // epilogue: bias + relu + red.v2 scatter
#pragma unroll
        for (int mt = 0; mt < 2; mt++) {
            int r_lo = wm * 32 + mt * 16 + grp;
            int r_hi = r_lo + 8;
            bool v_lo = (e0 + r_lo) < e_cnt;
            bool v_hi = (e0 + r_hi) < e_cnt;
            int d_lo = s_recv[r_lo];
            int d_hi = s_recv[r_hi];
#pragma unroll
            for (int nt = 0; nt < 8; nt++) {
                int col = wn * 64 + nt * 8 + tg * 2;
                float b0 = s_bias[col], b1 = s_bias[col + 1];
                if (v_lo)
                    red2(&agg[(size_t)d_lo * NF + col],
                         fmaxf(acc[mt][nt][0] + b0, 0.f),
                         fmaxf(acc[mt][nt][1] + b1, 0.f));
                if (v_hi)
                    red2(&agg[(size_t)d_hi * NF + col],
                         fmaxf(acc[mt][nt][2] + b0, 0.f),
                         fmaxf(acc[mt][nt][3] + b1, 0.f));
            }
        }
    }
}

// ---------------------------------------------------------------------------
// Particle propagator via mma.sync tf32: eff = relu([pe, agg] @ pp_w + pp_b)
// ---------------------------------------------------------------------------
#define PP_OFF_BIAS 0
#define PP_OFF_A0   512
#define PP_OFF_A1   (PP_OFF_A0 + 16384)
#define PP_OFF_B    (PP_OFF_A1 + 16384)            // 33280
#define PP_SMEM_BYTES (PP_OFF_B + 256 * 128 * 4)   // 164352

__global__ __launch_bounds__(256, 1) void k_part_prop_mma(
    const float* __restrict__ pe, const float* __restrict__ agg,
    const float* __restrict__ w, const float* __restrict__ b,
    float* __restrict__ eff, int n)
{
    extern __shared__ char smem[];
    float*    s_bias = (float*)   (smem + PP_OFF_BIAS);
    uint32_t* A0     = (uint32_t*)(smem + PP_OFF_A0);
    uint32_t* A1     = (uint32_t*)(smem + PP_OFF_A1);
    uint32_t* Bs     = (uint32_t*)(smem + PP_OFF_B);

    const int tid = threadIdx.x;
    const int wid = tid >> 5;
    const int lane = tid & 31;
    const int grp = lane >> 2;
    const int tg  = lane & 3;
    const int wm  = wid & 3;
    const int wn  = wid >> 2;

    for (int idx = tid; idx < 256 * 128; idx += 256) {
        int k = idx >> 7, nn = idx & 127;
        Bs[WSW(k, nn)] = cvt_tf32(w[k * NF + nn]);
    }
    if (tid < 128) s_bias[tid] = b[tid];
    __syncthreads();

    const int ntiles = (n + 127) >> 7;
    const int r_st   = tid >> 1;
    const int half   = tid & 1;

    for (int tile = blockIdx.x; tile < ntiles; tile += gridDim.x) {
        const int n0 = tile << 7;
        const int row = n0 + r_st;
        const bool rv = (row < n);

        float acc[2][8][4];
#pragma unroll
        for (int mt = 0; mt < 2; mt++)
#pragma unroll
            for (int nt = 0; nt < 8; nt++)
#pragma unroll
                for (int i = 0; i < 4; i++) acc[mt][nt][i] = 0.f;

        float4 pv[4];
        {
            const float* src = pe + (size_t)row * NF;   // chunk 0
#pragma unroll
            for (int q = 0; q < 4; q++)
                pv[q] = rv ? *(const float4*)(src + half * 16 + q * 4)
                           : make_float4(0.f, 0.f, 0.f, 0.f);
        }

        for (int c = 0; c < 8; c++) {
            uint32_t* Abuf = (c & 1) ? A1 : A0;
#pragma unroll
            for (int q = 0; q < 4; q++) {
                uint4 u = { cvt_tf32(pv[q].x), cvt_tf32(pv[q].y),
                            cvt_tf32(pv[q].z), cvt_tf32(pv[q].w) };
                *(uint4*)(Abuf + ACSW(r_st, half * 16 + q * 4)) = u;
            }
            __syncthreads();

            if (c < 7) {
                int cn = c + 1;
                const float* src = (cn < 4) ? pe  + (size_t)row * NF + cn * 32
                                            : agg + (size_t)row * NF + (cn - 4) * 32;
#pragma unroll
                for (int q = 0; q < 4; q++)
                    pv[q] = rv ? *(const float4*)(src + half * 16 + q * 4)
                               : make_float4(0.f, 0.f, 0.f, 0.f);
            }

            const int kb = c * 32;
#pragma unroll
            for (int s = 0; s < 4; s++) {
                const int ac = s * 8;
                const int kk = kb + ac;
                uint32_t bf[8][2];
#pragma unroll
                for (int nt = 0; nt < 8; nt++) {
                    int n_sw = (wn * 64 + nt * 8 + grp) ^ (tg << 3);
                    bf[nt][0] = Bs[((kk + tg) << 7) + n_sw];
                    bf[nt][1] = Bs[((kk + tg + 4) << 7) + n_sw];
                }
#pragma unroll
                for (int mt = 0; mt < 2; mt++) {
                    int rb = wm * 32 + mt * 16;
                    uint32_t af[4];
                    af[0] = Abuf[ACSW(rb + grp,     ac + tg)];
                    af[1] = Abuf[ACSW(rb + grp + 8, ac + tg)];
                    af[2] = Abuf[ACSW(rb + grp,     ac + tg + 4)];
                    af[3] = Abuf[ACSW(rb + grp + 8, ac + tg + 4)];
#pragma unroll
                    for (int nt = 0; nt < 8; nt++)
                        mma_tf32(acc[mt][nt], af, bf[nt]);
                }
            }
        }

        // epilogue: direct store
#pragma unroll
        for (int mt = 0; mt < 2; mt++) {
            int r_lo = wm * 32 + mt * 16 + grp;
            int r_hi = r_lo + 8;
            bool v_lo = (n0 + r_lo) < n;
            bool v_hi = (n0 + r_hi) < n;
#pragma unroll
            for (int nt = 0; nt < 8; nt++) {
                int col = wn * 64 + nt * 8 + tg * 2;
                float b0 = s_bias[col], b1 = s_bias[col + 1];
                if (v_lo) {
                    float2 v = { fmaxf(acc[mt][nt][0] + b0, 0.f),
                                 fmaxf(acc[mt][nt][1] + b1, 0.f) };
                    *(float2*)(eff + (size_t)(n0 + r_lo) * NF + col) = v;
                }
                if (v_hi) {
                    float2 v = { fmaxf(acc[mt][nt][2] + b0, 0.f),
                                 fmaxf(acc[mt][nt][3] + b1, 0.f) };
                    *(float2*)(eff + (size_t)(n0 + r_hi) * NF + col) = v;
                }
            }
        }
        __syncthreads();  // A buffers reused next tile
    }
}

// ---------------------------------------------------------------------------
// Decoder via mma.sync tf32: out = relu(relu(eff@w1+b1)@w2+b2) @ w3 + b3
// ---------------------------------------------------------------------------
#define DE_OFF_B1   0
#define DE_OFF_B2   512
#define DE_OFF_B3   1024       // 64 bytes reserved
#define DE_OFF_W3   1088       // 384*4 = 1536
#define DE_OFF_W1   2624
#define DE_OFF_W2   (DE_OFF_W1 + 65536)
#define DE_OFF_ACT  (DE_OFF_W2 + 65536)
#define DE_SMEM_BYTES (DE_OFF_ACT + 65536)   // 199232

__global__ __launch_bounds__(256, 1) void k_decoder_mma(
    const float* __restrict__ eff,
    const float* __restrict__ w1, const float* __restrict__ b1,
    const float* __restrict__ w2, const float* __restrict__ b2,
    const float* __restrict__ w3, const float* __restrict__ b3,
    float* __restrict__ out, int n)
{
    extern __shared__ char smem[];
    float*    s_b1 = (float*)   (smem + DE_OFF_B1);
    float*    s_b2 = (float*)   (smem + DE_OFF_B2);
    float*    s_b3 = (float*)   (smem + DE_OFF_B3);
    float*    s_w3 = (float*)   (smem + DE_OFF_W3);
    uint32_t* W1s  = (uint32_t*)(smem + DE_OFF_W1);
    uint32_t* W2s  = (uint32_t*)(smem + DE_OFF_W2);
    uint32_t* As   = (uint32_t*)(smem + DE_OFF_ACT);

    const int tid = threadIdx.x;
    const int wid = tid >> 5;
    const int lane = tid & 31;
    const int grp = lane >> 2;
    const int tg  = lane & 3;
    const int wm  = wid & 3;
    const int wn  = wid >> 2;

    for (int idx = tid; idx < 128 * 128; idx += 256) {
        int k = idx >> 7, nn = idx & 127;
        W1s[WSW(k, nn)] = cvt_tf32(w1[k * NF + nn]);
        W2s[WSW(k, nn)] = cvt_tf32(w2[k * NF + nn]);
    }
    for (int idx = tid; idx < 384; idx += 256) s_w3[idx] = w3[idx];
    if (tid < 128) { s_b1[tid] = b1[tid]; s_b2[tid] = b2[tid]; }
    if (tid < 3)   s_b3[tid] = b3[tid];
    __syncthreads();

    const int ntiles = (n + 127) >> 7;
    const int r_st   = tid >> 1;
    const int half   = tid & 1;

    float acc[2][8][4];

    for (int tile = blockIdx.x; tile < ntiles; tile += gridDim.x) {
        const int n0 = tile << 7;
        const int row = n0 + r_st;
        const bool rv = (row < n);

        // stage eff tile [128x128] tf32 swizzled (64 floats/thread)
        {
            const float* src = eff + (size_t)row * NF + half * 64;
#pragma unroll
            for (int q = 0; q < 16; q++) {
                float4 v = rv ? *(const float4*)(src + q * 4)
                              : make_float4(0.f, 0.f, 0.f, 0.f);
                uint4 u = { cvt_tf32(v.x), cvt_tf32(v.y), cvt_tf32(v.z), cvt_tf32(v.w) };
                *(uint4*)(As + ASW(r_st, half * 64 + q * 4)) = u;
            }
        }
        __syncthreads();

        // layer 1
#pragma unroll
        for (int mt = 0; mt < 2; mt++)
#pragma unroll
            for (int nt = 0; nt < 8; nt++)
#pragma unroll
                for (int i = 0; i < 4; i++) acc[mt][nt][i] = 0.f;
#pragma unroll
        for (int s = 0; s < 16; s++) {
            const int kk = s * 8;
            uint32_t bf[8][2];
#pragma unroll
            for (int nt = 0; nt < 8; nt++) {
                int n_sw = (wn * 64 + nt * 8 + grp) ^ (tg << 3);
                bf[nt][0] = W1s[((kk + tg) << 7) + n_sw];
                bf[nt][1] = W1s[((kk + tg + 4) << 7) + n_sw];
            }
#pragma unroll
            for (int mt = 0; mt < 2; mt++) {
                int rb = wm * 32 + mt * 16;
                uint32_t af[4];
                af[0] = As[ASW(rb + grp,     kk + tg)];
                af[1] = As[ASW(rb + grp + 8, kk + tg)];
                af[2] = As[ASW(rb + grp,     kk + tg + 4)];
                af[3] = As[ASW(rb + grp + 8, kk + tg + 4)];
#pragma unroll
                for (int nt = 0; nt < 8; nt++)
                    mma_tf32(acc[mt][nt], af, bf[nt]);
            }
        }
        __syncthreads();

#pragma unroll
        for (int mt = 0; mt < 2; mt++) {
            int r_lo = wm * 32 + mt * 16 + grp;
            int r_hi = r_lo + 8;
#pragma unroll
            for (int nt = 0; nt < 8; nt++) {
                int col = wn * 64 + nt * 8 + tg * 2;
                float b0 = s_b1[col], b1v = s_b1[col + 1];
                uint2 lo = { cvt_tf32(fmaxf(acc[mt][nt][0] + b0, 0.f)),
                             cvt_tf32(fmaxf(acc[mt][nt][1] + b1v, 0.f)) };
                uint2 hi = { cvt_tf32(fmaxf(acc[mt][nt][2] + b0, 0.f)),
                             cvt_tf32(fmaxf(acc[mt][nt][3] + b1v, 0.f)) };
                *(uint2*)(As + ASW(r_lo, col)) = lo;
                *(uint2*)(As + ASW(r_hi, col)) = hi;
            }
        }
        __syncthreads();

        // layer 2
#pragma unroll
        for (int mt = 0; mt < 2; mt++)
#pragma unroll
            for (int nt = 0; nt < 8; nt++)
#pragma unroll
                for (int i = 0; i < 4; i++) acc[mt][nt][i] = 0.f;
#pragma unroll
        for (int s = 0; s < 16; s++) {
            const int kk = s * 8;
            uint32_t bf[8][2];
#pragma unroll
            for (int nt = 0; nt < 8; nt++) {
                int n_sw = (wn * 64 + nt * 8 + grp) ^ (tg << 3);
                bf[nt][0] = W2s[((kk + tg) << 7) + n_sw];
                bf[nt][1] = W2s[((kk + tg + 4) << 7) + n_sw];
            }
#pragma unroll
            for (int mt = 0; mt < 2; mt++) {
                int rb = wm * 32 + mt * 16;
                uint32_t af[4];
                af[0] = As[ASW(rb + grp,     kk + tg)];
                af[1] = As[ASW(rb + grp + 8, kk + tg)];
                af[2] = As[ASW(rb + grp,     kk + tg + 4)];
                af[3] = As[ASW(rb + grp + 8, kk + tg + 4)];
#pragma unroll
                for (int nt = 0; nt < 8; nt++)
                    mma_tf32(acc[mt][nt], af, bf[nt]);
            }
        }
        __syncthreads();

        // write h2 (fp32 bits) into As
#pragma unroll
        for (int mt = 0; mt < 2; mt++) {
            int r_lo = wm * 32 + mt * 16 + grp;
            int r_hi = r_lo + 8;
#pragma unroll
            for (int nt = 0; nt < 8; nt++) {
                int col = wn * 64 + nt * 8 + tg * 2;
                float b0 = s_b2[col], b1v = s_b2[col + 1];
                uint2 lo = { __float_as_uint(fmaxf(acc[mt][nt][0] + b0, 0.f)),
                             __float_as_uint(fmaxf(acc[mt][nt][1] + b1v, 0.f)) };
                uint2 hi = { __float_as_uint(fmaxf(acc[mt][nt][2] + b0, 0.f)),
                             __float_as_uint(fmaxf(acc[mt][nt][3] + b1v, 0.f)) };
                *(uint2*)(As + ASW(r_lo, col)) = lo;
                *(uint2*)(As + ASW(r_hi, col)) = hi;
            }
        }
        __syncthreads();

        // final projection 128 -> 3 (scalar over smem)
        for (int d = tid; d < 128 * 3; d += 256) {
            int r = d / 3, j = d % 3;
            if (n0 + r < n) {
                float a = s_b3[j];
#pragma unroll 4
                for (int k = 0; k < NF; k++)
                    a = fmaf(__uint_as_float(As[ASW(r, k)]), s_w3[k * 3 + j], a);
                out[(size_t)(n0 + r) * 3 + j] = a;
            }
        }
        __syncthreads();  // As reused next tile
    }
}

// ---------------------------------------------------------------------------
// launch
// ---------------------------------------------------------------------------
extern "C" void kernel_launch(void* const* d_in, const int* in_sizes, int n_in,
                              void* d_out, int out_size)
{
    const float* attr  = (const float*)d_in[0];
    const float* state = (const float*)d_in[1];
    const float* Ra    = (const float*)d_in[2];
    const int*   recv  = (const int*)  d_in[3];
    const int*   send  = (const int*)  d_in[4];
    // d_in[5] = pstep (fixed 2)
    const float* pe_w1 = (const float*)d_in[6];
    const float* pe_b1 = (const float*)d_in[7];
    const float* pe_w2 = (const float*)d_in[8];
    const float* pe_b2 = (const float*)d_in[9];
    const float* ee_w1 = (const float*)d_in[10];
    const float* ee_b1 = (const float*)d_in[11];
    const float* ee_w2 = (const float*)d_in[12];
    const float* ee_b2 = (const float*)d_in[13];
    const float* ee_w3 = (const float*)d_in[14];
    const float* ee_b3 = (const float*)d_in[15];
    const float* rp_w  = (const float*)d_in[16];
    const float* rp_b  = (const float*)d_in[17];
    const float* pp_w  = (const float*)d_in[18];
    const float* pp_b  = (const float*)d_in[19];
    const float* de_w1 = (const float*)d_in[20];
    const float* de_b1 = (const float*)d_in[21];
    const float* de_w2 = (const float*)d_in[22];
    const float* de_b2 = (const float*)d_in[23];
    const float* de_w3 = (const float*)d_in[24];
    const float* de_b3 = (const float*)d_in[25];

    const int n = in_sizes[0] / ATTR_W;   // 100000
    const int e = in_sizes[2] / REL_W;    // 500000

    float *pe, *ee, *eff, *agg;
    cudaGetSymbolAddress((void**)&pe,  g_pe);
    cudaGetSymbolAddress((void**)&ee,  g_ee);
    cudaGetSymbolAddress((void**)&eff, g_eff);
    cudaGetSymbolAddress((void**)&agg, g_agg);

    cudaFuncSetAttribute(k_rel_prop_mma,
                         cudaFuncAttributeMaxDynamicSharedMemorySize, RP2_SMEM_BYTES);
    cudaFuncSetAttribute(k_edge_enc_mma,
                         cudaFuncAttributeMaxDynamicSharedMemorySize, EE_SMEM_BYTES);
    cudaFuncSetAttribute(k_part_prop_mma,
                         cudaFuncAttributeMaxDynamicSharedMemorySize, PP_SMEM_BYTES);
    cudaFuncSetAttribute(k_decoder_mma,
                         cudaFuncAttributeMaxDynamicSharedMemorySize, DE_SMEM_BYTES);

    const int RB_N = 8;
    dim3 blk(128);

    // effect starts at zero
    k_zero<<<1024, 256>>>(eff, n * NF);

    // encoders
    k_node_enc<<<(n + RB_N - 1) / RB_N, blk>>>(attr, state, pe_w1, pe_b1, pe_w2, pe_b2, pe, n);
    k_edge_enc_mma<<<148, 256, EE_SMEM_BYTES>>>(attr, state, Ra, recv, send,
                                                ee_w1, ee_b1, ee_w2, ee_b2, ee_w3, ee_b3, ee, e);

    // propagation (pstep = 2)
    for (int ps = 0; ps < PSTEP; ps++) {
        k_zero<<<1024, 256>>>(agg, n * NF);
        k_rel_prop_mma<<<148, 256, RP2_SMEM_BYTES>>>(ee, eff, recv, send, rp_w, rp_b, agg, e);
        k_part_prop_mma<<<148, 256, PP_SMEM_BYTES>>>(pe, agg, pp_w, pp_b, eff, n);
    }

    // decoder
    k_decoder_mma<<<148, 256, DE_SMEM_BYTES>>>(eff, de_w1, de_b1, de_w2, de_b2,
                                               de_w3, de_b3, (float*)d_out, n);
}